// round 7
// baseline (speedup 1.0000x reference)
#include <cuda_runtime.h>
#include <math.h>

// ---------------- problem constants ----------------
#define Bv   4
#define Rv   4
#define Nv   4096
#define Mv   64
#define KNv  12288
#define BRv  16
#define P1   196608
#define P2   1024
#define Fv   512
#define TILES2 1536          // P1 / 128
#define TPB2   96            // KN / 128 tiles per br

// ---------------- device scratch ----------------
__device__ int   d_topk[Bv * Nv * 3];
__device__ float d_csum[Bv * 2 * Mv];
__device__ float d_ccnt[Bv * Mv];
__device__ float d_nrot[BRv * 2 * Mv];
__device__ float d_g[130 * P2];
__device__ float d_fcol0[BRv * 128];
__device__ float d_A[256 * P2];
__device__ float d_B2[256 * P2];
__device__ float d_C2[512 * P2];
__device__ float d_D2[512 * P2];

// ---------------- packed f32x2 helpers ----------------
__device__ __forceinline__ unsigned long long ffma2(unsigned long long a,
                                                    unsigned long long b,
                                                    unsigned long long c) {
    unsigned long long d;
    asm("fma.rn.f32x2 %0, %1, %2, %3;" : "=l"(d) : "l"(a), "l"(b), "l"(c));
    return d;
}
__device__ __forceinline__ unsigned long long pack2(float lo, float hi) {
    unsigned long long r;
    asm("mov.b64 %0, {%1, %2};" : "=l"(r) : "f"(lo), "f"(hi));
    return r;
}
__device__ __forceinline__ float lo2(unsigned long long a) { return __uint_as_float((unsigned)a); }
__device__ __forceinline__ float hi2(unsigned long long a) { return __uint_as_float((unsigned)(a >> 32)); }

__device__ __forceinline__ void rot_cs(int r, float& c, float& s) {
    float th = 6.2831855f * (float)r * 0.25f;
    c = cosf(th);
    s = sinf(th);
}

// 8 outputs x 4 cols: weights wA(outs 0-3), wB(outs 4-7); act a = 4 cols (2 f32x2)
#define STEP8(wA, wB, a, acc)                                                            \
    do {                                                                                 \
        unsigned long long w0 = pack2((wA).x, (wA).x), w1 = pack2((wA).y, (wA).y);       \
        unsigned long long w2 = pack2((wA).z, (wA).z), w3 = pack2((wA).w, (wA).w);       \
        unsigned long long w4 = pack2((wB).x, (wB).x), w5 = pack2((wB).y, (wB).y);       \
        unsigned long long w6 = pack2((wB).z, (wB).z), w7 = pack2((wB).w, (wB).w);       \
        acc[0][0] = ffma2(w0, (a).x, acc[0][0]); acc[0][1] = ffma2(w0, (a).y, acc[0][1]); \
        acc[1][0] = ffma2(w1, (a).x, acc[1][0]); acc[1][1] = ffma2(w1, (a).y, acc[1][1]); \
        acc[2][0] = ffma2(w2, (a).x, acc[2][0]); acc[2][1] = ffma2(w2, (a).y, acc[2][1]); \
        acc[3][0] = ffma2(w3, (a).x, acc[3][0]); acc[3][1] = ffma2(w3, (a).y, acc[3][1]); \
        acc[4][0] = ffma2(w4, (a).x, acc[4][0]); acc[4][1] = ffma2(w4, (a).y, acc[4][1]); \
        acc[5][0] = ffma2(w5, (a).x, acc[5][0]); acc[5][1] = ffma2(w5, (a).y, acc[5][1]); \
        acc[6][0] = ffma2(w6, (a).x, acc[6][0]); acc[6][1] = ffma2(w6, (a).y, acc[6][1]); \
        acc[7][0] = ffma2(w7, (a).x, acc[7][0]); acc[7][1] = ffma2(w7, (a).y, acc[7][1]); \
    } while (0)

// ---------------- K0 ----------------
__global__ void k_init() {
    int i = blockIdx.x * 256 + threadIdx.x;
    if (i < Bv * 2 * Mv) d_csum[i] = 0.f;
    if (i < Bv * Mv)     d_ccnt[i] = 0.f;
    if (i < 130 * P2)    d_g[i]    = 0.f;
}

// ---------------- K1: top-3 + cluster accumulation ----------
__global__ void k_topk(const float* __restrict__ x, const float* __restrict__ node) {
    int idx = blockIdx.x * 256 + threadIdx.x;
    if (idx >= Bv * Nv) return;
    int b = idx >> 12, n = idx & (Nv - 1);
    float x0 = x[b * 2 * Nv + n];
    float x1 = x[b * 2 * Nv + Nv + n];
    float d0 = 3.4e38f, d1 = 3.4e38f, d2 = 3.4e38f;
    int   i0 = 0, i1 = 0, i2 = 0;
    #pragma unroll
    for (int m = 0; m < Mv; m++) {
        float dx = x0 - __ldg(&node[b * 2 * Mv + m]);
        float dy = x1 - __ldg(&node[b * 2 * Mv + Mv + m]);
        float d = dx * dx + dy * dy;
        if (d < d0)      { d2 = d1; i2 = i1; d1 = d0; i1 = i0; d0 = d; i0 = m; }
        else if (d < d1) { d2 = d1; i2 = i1; d1 = d;  i1 = m; }
        else if (d < d2) { d2 = d;  i2 = m; }
    }
    int o = idx * 3;
    d_topk[o] = i0; d_topk[o + 1] = i1; d_topk[o + 2] = i2;
    atomicAdd(&d_csum[b * 2 * Mv + i0],      x0);
    atomicAdd(&d_csum[b * 2 * Mv + Mv + i0], x1);
    atomicAdd(&d_ccnt[b * Mv + i0], 1.f);
    atomicAdd(&d_csum[b * 2 * Mv + i1],      x0);
    atomicAdd(&d_csum[b * 2 * Mv + Mv + i1], x1);
    atomicAdd(&d_ccnt[b * Mv + i1], 1.f);
    atomicAdd(&d_csum[b * 2 * Mv + i2],      x0);
    atomicAdd(&d_csum[b * 2 * Mv + Mv + i2], x1);
    atomicAdd(&d_ccnt[b * Mv + i2], 1.f);
}

// ---------------- K2 ----------------
__global__ void k_nodes() {
    int idx = threadIdx.x;
    int b = idx >> 6, m = idx & 63;
    float cnt = d_ccnt[b * Mv + m];
    float inv = 1.f / (cnt + 1e-5f);
    float m0 = d_csum[b * 2 * Mv + m]      * inv;
    float m1 = d_csum[b * 2 * Mv + Mv + m] * inv;
    #pragma unroll
    for (int r = 0; r < Rv; r++) {
        float c, s; rot_cs(r, c, s);
        float n0 = c * m0 - s * m1;
        float n1 = s * m0 + c * m1;
        int br = b * Rv + r;
        d_nrot[(br * 2 + 0) * Mv + m] = n0;
        d_nrot[(br * 2 + 1) * Mv + m] = n1;
        d_g[0 * P2 + br * Mv + m] = n0;
        d_g[1 * P2 + br * Mv + m] = n1;
    }
}

// ---------------- fused fp block (128-col tiles, 512 threads) --------------
// smem layout (float offsets)
#define SW0  0          // 128
#define SB0  128        // 64
#define SB1  192        // 64
#define SB2  256        // 128
#define SB3  384        // 128
#define SW1  512        // [64k][64o]   -> 4608
#define SXS  4608       // [2][128]     -> 4864
#define SMS  4864       // int[128]     -> 4992
#define SBA  4992       // [64k][128c]  -> 13184
#define SBB  13184      // [64k][128c]  -> 21376
#define SBC  21376      // [64k][128c]  -> 29568
#define SW2  29568      // [64k][128o]  -> 37760
#define SW3  37760      // [130k][128o] -> 54400
#define SMEM_FLOATS 54400

__global__ void __launch_bounds__(512, 1) k_fp(
    const float* __restrict__ x,
    const float* __restrict__ W0, const float* __restrict__ b0,
    const float* __restrict__ W1, const float* __restrict__ b1,
    const float* __restrict__ W2, const float* __restrict__ b2,
    const float* __restrict__ W3, const float* __restrict__ b3)
{
    extern __shared__ float sm[];
    const int tid = threadIdx.x;

    for (int i = tid; i < 128; i += 512) sm[SW0 + i] = W0[i];
    for (int i = tid; i < 64;  i += 512) { sm[SB0 + i] = b0[i]; sm[SB1 + i] = b1[i]; }
    for (int i = tid; i < 128; i += 512) { sm[SB2 + i] = b2[i]; sm[SB3 + i] = b3[i]; }
    for (int i = tid; i < 4096; i += 512) { int o = i & 63,  k = i >> 6; sm[SW1 + k * 64  + o] = W1[o * 64  + k]; }
    for (int i = tid; i < 8192; i += 512) { int o = i & 127, k = i >> 7; sm[SW2 + k * 128 + o] = W2[o * 64  + k]; }
    for (int i = tid; i < 130 * 128; i += 512) { int o = i & 127, k = i >> 7; sm[SW3 + k * 128 + o] = W3[o * 130 + k]; }
    __syncthreads();

    int* ms = (int*)(sm + SMS);
    const int og = tid >> 5;            // 0..15  (uniform per warp!)
    const int cg = tid & 31;            // 0..31
    const int p0 = cg * 4;              // 4 contiguous cols per thread

    for (int t = blockIdx.x; t < TILES2; t += gridDim.x) {
        int br = t / TPB2; int tloc = t - br * TPB2; int kn0 = tloc * 128;
        int b = br >> 2, r = br & 3;

        // ---- P0: xdec prologue ----
        if (tid < 128) {
            int kn = kn0 + tid; int k = kn >> 12; int n = kn & (Nv - 1);
            float x0 = x[b * 2 * Nv + n], x1 = x[b * 2 * Nv + Nv + n];
            float c, s; rot_cs(r, c, s);
            float xr0 = c * x0 - s * x1;
            float xr1 = s * x0 + c * x1;
            int m = d_topk[(b * Nv + n) * 3 + k];
            sm[SXS + tid]       = xr0 - d_nrot[(br * 2 + 0) * Mv + m];
            sm[SXS + 128 + tid] = xr1 - d_nrot[(br * 2 + 1) * Mv + m];
            ms[tid] = m;
        }
        __syncthreads();

        // ---- L0: 64 x 128, K=2 (4 outs x 4 cols per thread) ----
        {
            int o0 = og * 4;
            #pragma unroll
            for (int i = 0; i < 4; i++) {
                int o = o0 + i;
                float w0 = sm[SW0 + o * 2], w1 = sm[SW0 + o * 2 + 1], bb = sm[SB0 + o];
                float4 rv;
                rv.x = fmaxf(fmaf(w0, sm[SXS + p0 + 0], fmaf(w1, sm[SXS + 128 + p0 + 0], bb)), 0.f);
                rv.y = fmaxf(fmaf(w0, sm[SXS + p0 + 1], fmaf(w1, sm[SXS + 128 + p0 + 1], bb)), 0.f);
                rv.z = fmaxf(fmaf(w0, sm[SXS + p0 + 2], fmaf(w1, sm[SXS + 128 + p0 + 2], bb)), 0.f);
                rv.w = fmaxf(fmaf(w0, sm[SXS + p0 + 3], fmaf(w1, sm[SXS + 128 + p0 + 3], bb)), 0.f);
                *(float4*)&sm[SBA + o * 128 + p0] = rv;
            }
        }
        __syncthreads();

        // ---- L1: 64 x 128, K=64 (bA -> bB), 4 outs x 4 cols ----
        {
            int o0 = og * 4;
            unsigned long long acc[4][2];
            #pragma unroll
            for (int i = 0; i < 4; i++) { acc[i][0] = 0ull; acc[i][1] = 0ull; }
            #pragma unroll 4
            for (int kk = 0; kk < 64; kk++) {
                float4 w = *(const float4*)&sm[SW1 + kk * 64 + o0];   // warp-uniform
                ulonglong2 a = *(const ulonglong2*)&sm[SBA + kk * 128 + p0];
                unsigned long long w0 = pack2(w.x, w.x), w1 = pack2(w.y, w.y);
                unsigned long long w2 = pack2(w.z, w.z), w3 = pack2(w.w, w.w);
                acc[0][0] = ffma2(w0, a.x, acc[0][0]); acc[0][1] = ffma2(w0, a.y, acc[0][1]);
                acc[1][0] = ffma2(w1, a.x, acc[1][0]); acc[1][1] = ffma2(w1, a.y, acc[1][1]);
                acc[2][0] = ffma2(w2, a.x, acc[2][0]); acc[2][1] = ffma2(w2, a.y, acc[2][1]);
                acc[3][0] = ffma2(w3, a.x, acc[3][0]); acc[3][1] = ffma2(w3, a.y, acc[3][1]);
            }
            #pragma unroll
            for (int i = 0; i < 4; i++) {
                int o = o0 + i; float bv = sm[SB1 + o];
                float4 rv;
                rv.x = fmaxf(lo2(acc[i][0]) + bv, 0.f); rv.y = fmaxf(hi2(acc[i][0]) + bv, 0.f);
                rv.z = fmaxf(lo2(acc[i][1]) + bv, 0.f); rv.w = fmaxf(hi2(acc[i][1]) + bv, 0.f);
                *(float4*)&sm[SBB + o * 128 + p0] = rv;
            }
        }
        __syncthreads();

        // ---- L2: 128 x 128, K=64 (bB -> bA low / bC high), 8 outs x 4 cols ----
        {
            int o0 = og * 8;
            unsigned long long acc[8][2];
            #pragma unroll
            for (int i = 0; i < 8; i++) { acc[i][0] = 0ull; acc[i][1] = 0ull; }
            #pragma unroll 4
            for (int kk = 0; kk < 64; kk++) {
                float4 wA = *(const float4*)&sm[SW2 + kk * 128 + o0];
                float4 wB = *(const float4*)&sm[SW2 + kk * 128 + o0 + 4];
                ulonglong2 a = *(const ulonglong2*)&sm[SBB + kk * 128 + p0];
                STEP8(wA, wB, a, acc);
            }
            float* dst = (o0 < 64) ? (sm + SBA + o0 * 128) : (sm + SBC + (o0 - 64) * 128);
            #pragma unroll
            for (int i = 0; i < 8; i++) {
                float bv = sm[SB2 + o0 + i];
                float4 rv;
                rv.x = fmaxf(lo2(acc[i][0]) + bv, 0.f); rv.y = fmaxf(hi2(acc[i][0]) + bv, 0.f);
                rv.z = fmaxf(lo2(acc[i][1]) + bv, 0.f); rv.w = fmaxf(hi2(acc[i][1]) + bv, 0.f);
                *(float4*)&dst[i * 128 + p0] = rv;
            }
        }
        __syncthreads();

        // ---- L3: 128 x 128, K=130 -> scatter-max, 8 outs x 4 cols ----
        {
            int o0 = og * 8;
            unsigned long long acc[8][2];
            #pragma unroll
            for (int i = 0; i < 8; i++) { acc[i][0] = 0ull; acc[i][1] = 0ull; }
            #pragma unroll
            for (int k = 0; k < 2; k++) {
                float4 wA = *(const float4*)&sm[SW3 + k * 128 + o0];
                float4 wB = *(const float4*)&sm[SW3 + k * 128 + o0 + 4];
                ulonglong2 a = *(const ulonglong2*)&sm[SXS + k * 128 + p0];
                STEP8(wA, wB, a, acc);
            }
            #pragma unroll 4
            for (int kk = 0; kk < 64; kk++) {                  // h3 rows 0-63 in bA
                float4 wA = *(const float4*)&sm[SW3 + (2 + kk) * 128 + o0];
                float4 wB = *(const float4*)&sm[SW3 + (2 + kk) * 128 + o0 + 4];
                ulonglong2 a = *(const ulonglong2*)&sm[SBA + kk * 128 + p0];
                STEP8(wA, wB, a, acc);
            }
            #pragma unroll 4
            for (int kk = 0; kk < 64; kk++) {                  // h3 rows 64-127 in bC
                float4 wA = *(const float4*)&sm[SW3 + (66 + kk) * 128 + o0];
                float4 wB = *(const float4*)&sm[SW3 + (66 + kk) * 128 + o0 + 4];
                ulonglong2 a = *(const ulonglong2*)&sm[SBC + kk * 128 + p0];
                STEP8(wA, wB, a, acc);
            }
            // epilogue: bias + relu + scatter-max
            int mc[4];
            #pragma unroll
            for (int j = 0; j < 4; j++) mc[j] = ms[p0 + j];
            #pragma unroll
            for (int i = 0; i < 8; i++) {
                int o = o0 + i; float bv = sm[SB3 + o];
                unsigned* gp = (unsigned*)&d_g[(2 + o) * P2 + br * Mv];
                float v0 = fmaxf(lo2(acc[i][0]) + bv, 0.f);
                float v1 = fmaxf(hi2(acc[i][0]) + bv, 0.f);
                float v2 = fmaxf(lo2(acc[i][1]) + bv, 0.f);
                float v3 = fmaxf(hi2(acc[i][1]) + bv, 0.f);
                atomicMax(gp + mc[0], __float_as_uint(v0));
                atomicMax(gp + mc[1], __float_as_uint(v1));
                atomicMax(gp + mc[2], __float_as_uint(v2));
                atomicMax(gp + mc[3], __float_as_uint(v3));
                if (tloc == 0 && cg == 0)
                    d_fcol0[br * 128 + o] = v0;   // feat[:, :, 0]
            }
        }
        __syncthreads();
    }
}

// ---------------- K5: empty-cluster fallback ----------------
__global__ void k_fix() {
    int idx = blockIdx.x * 256 + threadIdx.x;
    int m = idx & 63; int c = (idx >> 6) & 127; int br = idx >> 13;
    int b = br >> 2;
    if (d_ccnt[b * Mv + m] == 0.f)
        d_g[(2 + c) * P2 + br * Mv + m] = d_fcol0[br * 128 + c];
}

// ---------------- gp GEMM + bias + ReLU (warp-uniform weights) -------------
__global__ void __launch_bounds__(256) k_gemm(
    const float* __restrict__ W, const float* __restrict__ bias,
    const float* __restrict__ in1, int C1,
    const float* __restrict__ in2, int C2,
    float* __restrict__ out, int P)
{
    __shared__ __align__(16) float Wsh[16][68];
    __shared__ __align__(16) float Ish[16][68];
    const int C = C1 + C2;
    const int col0 = blockIdx.x * 64, ob0 = blockIdx.y * 64;
    const int tid = threadIdx.x;
    const int og = tid >> 5;            // 0..7 (uniform per warp)
    const int cg = tid & 31;
    // 8 outs x 2 cols per thread: outs ob0+og*8.., cols col0+cg*2..
    const int o0 = og * 8, p0 = cg * 2;
    unsigned long long acc[8];
    #pragma unroll
    for (int i = 0; i < 8; i++) acc[i] = 0ull;

    for (int k0 = 0; k0 < C; k0 += 16) {
        #pragma unroll
        for (int q = 0; q < 4; q++) {
            int l = tid * 4 + q; int oo = l >> 4, kk = l & 15;
            int c = k0 + kk;
            Wsh[kk][oo] = (c < C) ? W[(ob0 + oo) * C + c] : 0.f;
        }
        #pragma unroll
        for (int q = 0; q < 4; q++) {
            int l = tid * 4 + q; int kk = l >> 6, cc = l & 63;
            int c = k0 + kk;
            float v = 0.f;
            if (c < C1)      v = in1[c * P + col0 + cc];
            else if (c < C)  v = in2[(c - C1) * P + col0 + cc];
            Ish[kk][cc] = v;
        }
        __syncthreads();
        #pragma unroll
        for (int kk = 0; kk < 16; kk++) {
            float4 wA = *(const float4*)&Wsh[kk][o0];
            float4 wB = *(const float4*)&Wsh[kk][o0 + 4];
            unsigned long long a = *(const unsigned long long*)&Ish[kk][p0];
            acc[0] = ffma2(pack2(wA.x, wA.x), a, acc[0]);
            acc[1] = ffma2(pack2(wA.y, wA.y), a, acc[1]);
            acc[2] = ffma2(pack2(wA.z, wA.z), a, acc[2]);
            acc[3] = ffma2(pack2(wA.w, wA.w), a, acc[3]);
            acc[4] = ffma2(pack2(wB.x, wB.x), a, acc[4]);
            acc[5] = ffma2(pack2(wB.y, wB.y), a, acc[5]);
            acc[6] = ffma2(pack2(wB.z, wB.z), a, acc[6]);
            acc[7] = ffma2(pack2(wB.w, wB.w), a, acc[7]);
        }
        __syncthreads();
    }
    #pragma unroll
    for (int i = 0; i < 8; i++) {
        int o = ob0 + o0 + i;
        float bv = bias[o];
        float vl = fmaxf(lo2(acc[i]) + bv, 0.f);
        float vh = fmaxf(hi2(acc[i]) + bv, 0.f);
        *(float2*)&out[o * P + col0 + p0] = make_float2(vl, vh);
    }
}

// ---------------- K6: final max over (r, m) ----------------
__global__ void k_reduce(float* __restrict__ out) {
    int idx = blockIdx.x * 256 + threadIdx.x;
    int b = idx >> 9, f = idx & 511;
    const float* src = &d_D2[f * P2 + b * 256];
    float v = 0.f;
    #pragma unroll 8
    for (int j = 0; j < 256; j++) v = fmaxf(v, src[j]);
    out[b * Fv + f] = v;
}

// ---------------- host launcher ----------------
extern "C" void kernel_launch(void* const* d_in, const int* in_sizes, int n_in,
                              void* d_out, int out_size) {
    const float* x    = (const float*)d_in[0];
    const float* node = (const float*)d_in[2];
    const float* fpW0 = (const float*)d_in[4];  const float* fpb0 = (const float*)d_in[5];
    const float* fpW1 = (const float*)d_in[6];  const float* fpb1 = (const float*)d_in[7];
    const float* fpW2 = (const float*)d_in[8];  const float* fpb2 = (const float*)d_in[9];
    const float* fpW3 = (const float*)d_in[10]; const float* fpb3 = (const float*)d_in[11];
    const float* gpW0 = (const float*)d_in[12]; const float* gpb0 = (const float*)d_in[13];
    const float* gpW1 = (const float*)d_in[14]; const float* gpb1 = (const float*)d_in[15];
    const float* gpW2 = (const float*)d_in[16]; const float* gpb2 = (const float*)d_in[17];
    const float* gpW3 = (const float*)d_in[18]; const float* gpb3 = (const float*)d_in[19];

    float *p_g, *p_A, *p_B2, *p_C2, *p_D2;
    cudaGetSymbolAddress((void**)&p_g,  d_g);
    cudaGetSymbolAddress((void**)&p_A,  d_A);
    cudaGetSymbolAddress((void**)&p_B2, d_B2);
    cudaGetSymbolAddress((void**)&p_C2, d_C2);
    cudaGetSymbolAddress((void**)&p_D2, d_D2);

    cudaFuncSetAttribute(k_fp, cudaFuncAttributeMaxDynamicSharedMemorySize,
                         SMEM_FLOATS * 4);

    k_init<<<(130 * P2 + 255) / 256, 256>>>();
    k_topk<<<(Bv * Nv) / 256, 256>>>(x, node);
    k_nodes<<<1, 256>>>();

    k_fp<<<148, 512, SMEM_FLOATS * 4>>>(x, fpW0, fpb0, fpW1, fpb1,
                                        fpW2, fpb2, fpW3, fpb3);
    k_fix<<<(BRv * 128 * Mv) / 256, 256>>>();

    k_gemm<<<dim3(P2 / 64, 4), 256>>>(gpW0, gpb0, p_g,  130, nullptr, 0,   p_A,  P2);
    k_gemm<<<dim3(P2 / 64, 4), 256>>>(gpW1, gpb1, p_A,  256, nullptr, 0,   p_B2, P2);
    k_gemm<<<dim3(P2 / 64, 8), 256>>>(gpW2, gpb2, p_B2, 256, nullptr, 0,   p_C2, P2);
    k_gemm<<<dim3(P2 / 64, 8), 256>>>(gpW3, gpb3, p_g,  130, p_C2,  512,   p_D2, P2);

    k_reduce<<<(Bv * Fv) / 256, 256>>>((float*)d_out);
}

// round 9
// speedup vs baseline: 1.1259x; 1.1259x over previous
#include <cuda_runtime.h>
#include <cuda_bf16.h>
#include <math.h>
#include <stdint.h>

// ---------------- problem constants ----------------
#define Bv   4
#define Rv   4
#define Nv   4096
#define Mv   64
#define KNv  12288
#define BRv  16
#define P1   196608
#define P2   1024
#define Fv   512
#define TILES2 1536          // P1 / 128
#define TPB2   96            // KN / 128 tiles per br

// ---------------- device scratch ----------------
__device__ int   d_topk[Bv * Nv * 3];
__device__ float d_csum[Bv * 2 * Mv];
__device__ float d_ccnt[Bv * Mv];
__device__ float d_nrot[BRv * 2 * Mv];
__device__ float d_g[130 * P2];
__device__ float d_fcol0[BRv * 128];
__device__ float d_A[256 * P2];
__device__ float d_B2[256 * P2];
__device__ float d_C2[512 * P2];
__device__ float d_D2[512 * P2];

// ---------------- scalar helpers ----------------
__device__ __forceinline__ unsigned long long ffma2(unsigned long long a,
                                                    unsigned long long b,
                                                    unsigned long long c) {
    unsigned long long d;
    asm("fma.rn.f32x2 %0, %1, %2, %3;" : "=l"(d) : "l"(a), "l"(b), "l"(c));
    return d;
}
__device__ __forceinline__ unsigned long long pack2(float lo, float hi) {
    unsigned long long r;
    asm("mov.b64 %0, {%1, %2};" : "=l"(r) : "f"(lo), "f"(hi));
    return r;
}
__device__ __forceinline__ float lo2(unsigned long long a) { return __uint_as_float((unsigned)a); }
__device__ __forceinline__ float hi2(unsigned long long a) { return __uint_as_float((unsigned)(a >> 32)); }

__device__ __forceinline__ void rot_cs(int r, float& c, float& s) {
    float th = 6.2831855f * (float)r * 0.25f;
    c = cosf(th);
    s = sinf(th);
}
__device__ __forceinline__ uint32_t smem_u32(const void* p) {
    uint32_t a;
    asm("{ .reg .u64 t; cvta.to.shared.u64 t, %1; cvt.u32.u64 %0, t; }" : "=r"(a) : "l"(p));
    return a;
}
__device__ __forceinline__ uint32_t swz(uint32_t b) { return b ^ ((b >> 3) & 0x70); }

// ---------------- warp MMA helpers (sm_80-class, compiles for compute_103) --
__device__ __forceinline__ void ldsm4(uint32_t* r, uint32_t addr) {
    asm volatile("ldmatrix.sync.aligned.m8n8.x4.shared.b16 {%0,%1,%2,%3}, [%4];"
                 : "=r"(r[0]), "=r"(r[1]), "=r"(r[2]), "=r"(r[3]) : "r"(addr));
}
__device__ __forceinline__ void mma16816(float* d, const uint32_t* a, const uint32_t* b) {
    asm volatile("mma.sync.aligned.m16n8k16.row.col.f32.bf16.bf16.f32 "
                 "{%0,%1,%2,%3}, {%4,%5,%6,%7}, {%8,%9}, {%0,%1,%2,%3};"
                 : "+f"(d[0]), "+f"(d[1]), "+f"(d[2]), "+f"(d[3])
                 : "r"(a[0]), "r"(a[1]), "r"(a[2]), "r"(a[3]), "r"(b[0]), "r"(b[1]));
}

// one pass over K=64 of one (act, weight) tile pair; NT n-tiles (8 outs each)
template<int NT>
__device__ __forceinline__ void mma_pass(float acc[][4], uint32_t actBase, uint32_t wBase,
                                         int mt, int n0, int lane) {
    const int arow = 16 * mt + (lane & 7) + ((lane >> 3) & 1) * 8;
    const int aoff = ((lane >> 4) & 1) * 16;
    const int brow = (lane & 7) + (lane >> 4) * 8;
    const int boff = ((lane >> 3) & 1) * 16;
    #pragma unroll
    for (int ks = 0; ks < 4; ks++) {
        uint32_t a[4];
        ldsm4(a, actBase + swz((uint32_t)(arow * 128 + 32 * ks + aoff)));
        #pragma unroll
        for (int tp = 0; tp < NT / 2; tp++) {
            uint32_t bf[4];
            ldsm4(bf, wBase + swz((uint32_t)((n0 + 16 * tp + brow) * 128 + 32 * ks + boff)));
            mma16816(acc[2 * tp],     a, bf);
            mma16816(acc[2 * tp + 1], a, bf + 2);
        }
    }
}

// hi/lo 3-pass accumulate
template<int NT>
__device__ __forceinline__ void mma3(float acc[][4], uint32_t aH, uint32_t aL,
                                     uint32_t wH, uint32_t wL, int mt, int n0, int lane) {
    mma_pass<NT>(acc, aH, wH, mt, n0, lane);
    mma_pass<NT>(acc, aH, wL, mt, n0, lane);
    mma_pass<NT>(acc, aL, wH, mt, n0, lane);
}

// store bf16 hi/lo pair (cols o, o+1) at point row p
__device__ __forceinline__ void st_pair(uint32_t hB, uint32_t lB, int p, int o,
                                        float v0, float v1) {
    uint32_t h, l;
    asm("cvt.rn.bf16x2.f32 %0, %1, %2;" : "=r"(h) : "f"(v1), "f"(v0));
    float h0 = __uint_as_float(h << 16);
    float h1 = __uint_as_float(h & 0xffff0000u);
    asm("cvt.rn.bf16x2.f32 %0, %1, %2;" : "=r"(l) : "f"(v1 - h1), "f"(v0 - h0));
    uint32_t off = swz((uint32_t)(p * 128 + 2 * o));
    asm volatile("st.shared.b32 [%0], %1;" :: "r"(hB + off), "r"(h) : "memory");
    asm volatile("st.shared.b32 [%0], %1;" :: "r"(lB + off), "r"(l) : "memory");
}

// pack 8 fp32 -> 16B bf16-hi + 16B bf16-lo (for L0)
__device__ __forceinline__ void pack_store8(uint32_t addrH, uint32_t addrL, const float* v) {
    uint32_t h[4], l[4];
    #pragma unroll
    for (int q = 0; q < 4; q++) {
        float a = v[2 * q], b = v[2 * q + 1];
        asm("cvt.rn.bf16x2.f32 %0, %1, %2;" : "=r"(h[q]) : "f"(b), "f"(a));
        float ha = __uint_as_float(h[q] << 16);
        float hb = __uint_as_float(h[q] & 0xffff0000u);
        asm("cvt.rn.bf16x2.f32 %0, %1, %2;" : "=r"(l[q]) : "f"(b - hb), "f"(a - ha));
    }
    asm volatile("st.shared.v4.b32 [%0], {%1, %2, %3, %4};"
                 :: "r"(addrH), "r"(h[0]), "r"(h[1]), "r"(h[2]), "r"(h[3]) : "memory");
    asm volatile("st.shared.v4.b32 [%0], {%1, %2, %3, %4};"
                 :: "r"(addrL), "r"(l[0]), "r"(l[1]), "r"(l[2]), "r"(l[3]) : "memory");
}

// ---------------- K0 ----------------
__global__ void k_init() {
    int i = blockIdx.x * 256 + threadIdx.x;
    if (i < Bv * 2 * Mv) d_csum[i] = 0.f;
    if (i < Bv * Mv)     d_ccnt[i] = 0.f;
    if (i < 130 * P2)    d_g[i]    = 0.f;
}

// ---------------- K1: top-3 + cluster accumulation ----------
__global__ void k_topk(const float* __restrict__ x, const float* __restrict__ node) {
    int idx = blockIdx.x * 256 + threadIdx.x;
    if (idx >= Bv * Nv) return;
    int b = idx >> 12, n = idx & (Nv - 1);
    float x0 = x[b * 2 * Nv + n];
    float x1 = x[b * 2 * Nv + Nv + n];
    float d0 = 3.4e38f, d1 = 3.4e38f, d2 = 3.4e38f;
    int   i0 = 0, i1 = 0, i2 = 0;
    #pragma unroll
    for (int m = 0; m < Mv; m++) {
        float dx = x0 - __ldg(&node[b * 2 * Mv + m]);
        float dy = x1 - __ldg(&node[b * 2 * Mv + Mv + m]);
        float d = dx * dx + dy * dy;
        if (d < d0)      { d2 = d1; i2 = i1; d1 = d0; i1 = i0; d0 = d; i0 = m; }
        else if (d < d1) { d2 = d1; i2 = i1; d1 = d;  i1 = m; }
        else if (d < d2) { d2 = d;  i2 = m; }
    }
    int o = idx * 3;
    d_topk[o] = i0; d_topk[o + 1] = i1; d_topk[o + 2] = i2;
    atomicAdd(&d_csum[b * 2 * Mv + i0],      x0);
    atomicAdd(&d_csum[b * 2 * Mv + Mv + i0], x1);
    atomicAdd(&d_ccnt[b * Mv + i0], 1.f);
    atomicAdd(&d_csum[b * 2 * Mv + i1],      x0);
    atomicAdd(&d_csum[b * 2 * Mv + Mv + i1], x1);
    atomicAdd(&d_ccnt[b * Mv + i1], 1.f);
    atomicAdd(&d_csum[b * 2 * Mv + i2],      x0);
    atomicAdd(&d_csum[b * 2 * Mv + Mv + i2], x1);
    atomicAdd(&d_ccnt[b * Mv + i2], 1.f);
}

// ---------------- K2 ----------------
__global__ void k_nodes() {
    int idx = threadIdx.x;
    int b = idx >> 6, m = idx & 63;
    float cnt = d_ccnt[b * Mv + m];
    float inv = 1.f / (cnt + 1e-5f);
    float m0 = d_csum[b * 2 * Mv + m]      * inv;
    float m1 = d_csum[b * 2 * Mv + Mv + m] * inv;
    #pragma unroll
    for (int r = 0; r < Rv; r++) {
        float c, s; rot_cs(r, c, s);
        float n0 = c * m0 - s * m1;
        float n1 = s * m0 + c * m1;
        int br = b * Rv + r;
        d_nrot[(br * 2 + 0) * Mv + m] = n0;
        d_nrot[(br * 2 + 1) * Mv + m] = n1;
        d_g[0 * P2 + br * Mv + m] = n0;
        d_g[1 * P2 + br * Mv + m] = n1;
    }
}

// ---------------- warp-MMA fused fp block ----------------
// smem byte offsets (bf16 tiles: [row][64k] = 128B rows, SW128, 1024-aligned)
#define OW1H  0         // W1 hi  [64o][64k]
#define OW1L  8192
#define OW2H  16384     // W2 hi  [128o][64k]
#define OW2L  32768
#define OW3AH 49152     // W3 k=2..65
#define OW3AL 65536
#define OW3BH 81920     // W3 k=66..129
#define OW3BL 98304
#define OBAH  114688    // act tile A (L0 out / L1 in; reused: h3 ch 0-63)
#define OBAL  131072
#define ORH   147456    // act tile R (L1 out / L2 in)
#define ORL   163840
#define OCBH  180224    // h3 ch 64-127
#define OCBL  196608
#define OW0F  212992    // W0 fp32 [128]
#define OW3X  213504    // W3 x-part fp32 [256]
#define OB0   214528
#define OB1   214784
#define OB2   215040
#define OB3   215552
#define OXS   216064    // xdec fp32 [256]
#define OMS   217088    // int [128]
#define SMEM_TC 217600

__global__ void __launch_bounds__(512, 1) k_fp_mma(
    const float* __restrict__ x,
    const float* __restrict__ W0, const float* __restrict__ b0,
    const float* __restrict__ W1, const float* __restrict__ b1,
    const float* __restrict__ W2, const float* __restrict__ b2,
    const float* __restrict__ W3, const float* __restrict__ b3)
{
    extern __shared__ __align__(1024) char smc[];
    float* smf = (float*)smc;
    const int tid  = threadIdx.x;
    const int wid  = tid >> 5;
    const int lane = tid & 31;
    const uint32_t sb = smem_u32(smc);

    // ---- one-time: weights -> bf16 hi/lo swizzled K-major tiles ----
    for (int i = tid; i < 4096; i += 512) {
        int o = i >> 6, k = i & 63;
        float w = W1[o * 64 + k];
        __nv_bfloat16 h = __float2bfloat16(w);
        __nv_bfloat16 l = __float2bfloat16(w - __bfloat162float(h));
        uint32_t off = swz(o * 128 + 2 * k);
        *(__nv_bfloat16*)(smc + OW1H + off) = h;
        *(__nv_bfloat16*)(smc + OW1L + off) = l;
    }
    for (int i = tid; i < 8192; i += 512) {
        int o = i >> 6, k = i & 63;
        float w = W2[o * 64 + k];
        __nv_bfloat16 h = __float2bfloat16(w);
        __nv_bfloat16 l = __float2bfloat16(w - __bfloat162float(h));
        uint32_t off = swz(o * 128 + 2 * k);
        *(__nv_bfloat16*)(smc + OW2H + off) = h;
        *(__nv_bfloat16*)(smc + OW2L + off) = l;
    }
    for (int i = tid; i < 8192; i += 512) {
        int o = i >> 6, k = i & 63;
        float w = W3[o * 130 + 2 + k];
        __nv_bfloat16 h = __float2bfloat16(w);
        __nv_bfloat16 l = __float2bfloat16(w - __bfloat162float(h));
        uint32_t off = swz(o * 128 + 2 * k);
        *(__nv_bfloat16*)(smc + OW3AH + off) = h;
        *(__nv_bfloat16*)(smc + OW3AL + off) = l;
    }
    for (int i = tid; i < 8192; i += 512) {
        int o = i >> 6, k = i & 63;
        float w = W3[o * 130 + 66 + k];
        __nv_bfloat16 h = __float2bfloat16(w);
        __nv_bfloat16 l = __float2bfloat16(w - __bfloat162float(h));
        uint32_t off = swz(o * 128 + 2 * k);
        *(__nv_bfloat16*)(smc + OW3BH + off) = h;
        *(__nv_bfloat16*)(smc + OW3BL + off) = l;
    }
    if (tid < 128) {
        smf[OW0F / 4 + tid] = W0[tid];
        smf[OW3X / 4 + tid]       = W3[tid * 130];
        smf[OW3X / 4 + 128 + tid] = W3[tid * 130 + 1];
        if (tid < 64) { smf[OB0 / 4 + tid] = b0[tid]; smf[OB1 / 4 + tid] = b1[tid]; }
        smf[OB2 / 4 + tid] = b2[tid];
        smf[OB3 / 4 + tid] = b3[tid];
    }
    __syncthreads();

    int* ms = (int*)(smc + OMS);
    const int mt = wid >> 1;          // m-tile 0..7 (16 points each)
    const int nh = wid & 1;           // n-half
    const int g  = lane >> 2;         // 0..7
    const int tq = lane & 3;          // 0..3
    const int rp = 16 * mt + g;       // point row (and rp+8)

    for (int t = blockIdx.x; t < TILES2; t += gridDim.x) {
        int br = t / TPB2; int tloc = t - br * TPB2; int kn0 = tloc * 128;
        int b = br >> 2, r = br & 3;

        // ---- P0: xdec (fp32, exact) ----
        if (tid < 128) {
            int kn = kn0 + tid; int k = kn >> 12; int n = kn & (Nv - 1);
            float x0 = x[b * 2 * Nv + n], x1 = x[b * 2 * Nv + Nv + n];
            float cc, ss; rot_cs(r, cc, ss);
            float xr0 = cc * x0 - ss * x1;
            float xr1 = ss * x0 + cc * x1;
            int m = d_topk[(b * Nv + n) * 3 + k];
            smf[OXS / 4 + tid]       = xr0 - d_nrot[(br * 2 + 0) * Mv + m];
            smf[OXS / 4 + 128 + tid] = xr1 - d_nrot[(br * 2 + 1) * Mv + m];
            ms[tid] = m;
        }
        __syncthreads();

        // ---- L0 scalar (K=2): h1 -> tile A ----
        {
            int pp = tid & 127, q = tid >> 7;
            float x0 = smf[OXS / 4 + pp], x1 = smf[OXS / 4 + 128 + pp];
            float v[16];
            #pragma unroll
            for (int j = 0; j < 16; j++) {
                int o = 16 * q + j;
                v[j] = fmaxf(fmaf(smf[OW0F / 4 + 2 * o], x0,
                             fmaf(smf[OW0F / 4 + 2 * o + 1], x1, smf[OB0 / 4 + o])), 0.f);
            }
            uint32_t ro = pp * 128 + 32 * q;
            pack_store8(sb + OBAH + swz(ro),      sb + OBAL + swz(ro),      v);
            pack_store8(sb + OBAH + swz(ro + 16), sb + OBAL + swz(ro + 16), v + 8);
        }
        __syncthreads();

        // ---- L1: h2 = relu(h1 x W1 + b1), N=64 ----
        {
            float acc[4][4];
            #pragma unroll
            for (int i = 0; i < 4; i++)
                #pragma unroll
                for (int j = 0; j < 4; j++) acc[i][j] = 0.f;
            int n0 = nh * 32;
            mma3<4>(acc, sb + OBAH, sb + OBAL, sb + OW1H, sb + OW1L, mt, n0, lane);
            #pragma unroll
            for (int nt = 0; nt < 4; nt++) {
                int o = n0 + 8 * nt + 2 * tq;
                float bv0 = smf[OB1 / 4 + o], bv1 = smf[OB1 / 4 + o + 1];
                st_pair(sb + ORH, sb + ORL, rp, o,
                        fmaxf(acc[nt][0] + bv0, 0.f), fmaxf(acc[nt][1] + bv1, 0.f));
                st_pair(sb + ORH, sb + ORL, rp + 8, o,
                        fmaxf(acc[nt][2] + bv0, 0.f), fmaxf(acc[nt][3] + bv1, 0.f));
            }
        }
        __syncthreads();

        // ---- L2: h3 = relu(h2 x W2 + b2), N=128 -> tiles A (o<64) / CB ----
        {
            float acc[8][4];
            #pragma unroll
            for (int i = 0; i < 8; i++)
                #pragma unroll
                for (int j = 0; j < 4; j++) acc[i][j] = 0.f;
            int n0 = nh * 64;
            mma3<8>(acc, sb + ORH, sb + ORL, sb + OW2H, sb + OW2L, mt, n0, lane);
            uint32_t hB = nh ? (sb + OCBH) : (sb + OBAH);
            uint32_t lB = nh ? (sb + OCBL) : (sb + OBAL);
            #pragma unroll
            for (int nt = 0; nt < 8; nt++) {
                int o = n0 + 8 * nt + 2 * tq;
                float bv0 = smf[OB2 / 4 + o], bv1 = smf[OB2 / 4 + o + 1];
                int oc = o & 63;
                st_pair(hB, lB, rp, oc,
                        fmaxf(acc[nt][0] + bv0, 0.f), fmaxf(acc[nt][1] + bv1, 0.f));
                st_pair(hB, lB, rp + 8, oc,
                        fmaxf(acc[nt][2] + bv0, 0.f), fmaxf(acc[nt][3] + bv1, 0.f));
            }
        }
        __syncthreads();

        // ---- L3: feat = relu(concat(x,h3) x W3 + b3), N=128 -> scatter-max ----
        {
            float acc[8][4];
            #pragma unroll
            for (int i = 0; i < 8; i++)
                #pragma unroll
                for (int j = 0; j < 4; j++) acc[i][j] = 0.f;
            int n0 = nh * 64;
            mma3<8>(acc, sb + OBAH, sb + OBAL, sb + OW3AH, sb + OW3AL, mt, n0, lane);
            mma3<8>(acc, sb + OCBH, sb + OCBL, sb + OW3BH, sb + OW3BL, mt, n0, lane);

            float x0a = smf[OXS / 4 + rp],     x1a = smf[OXS / 4 + 128 + rp];
            float x0b = smf[OXS / 4 + rp + 8], x1b = smf[OXS / 4 + 128 + rp + 8];
            int ma = ms[rp], mb = ms[rp + 8];
            unsigned* gpa = (unsigned*)&d_g[2 * P2 + br * Mv + ma];
            unsigned* gpb = (unsigned*)&d_g[2 * P2 + br * Mv + mb];
            bool put0 = (tloc == 0 && rp == 0);
            #pragma unroll
            for (int nt = 0; nt < 8; nt++) {
                int o = n0 + 8 * nt + 2 * tq;
                float w00 = smf[OW3X / 4 + o],       w10 = smf[OW3X / 4 + 128 + o];
                float w01 = smf[OW3X / 4 + o + 1],   w11 = smf[OW3X / 4 + 128 + o + 1];
                float bv0 = smf[OB3 / 4 + o],        bv1 = smf[OB3 / 4 + o + 1];
                float v0 = fmaxf(acc[nt][0] + bv0 + w00 * x0a + w10 * x1a, 0.f);
                float v1 = fmaxf(acc[nt][1] + bv1 + w01 * x0a + w11 * x1a, 0.f);
                float v2 = fmaxf(acc[nt][2] + bv0 + w00 * x0b + w10 * x1b, 0.f);
                float v3 = fmaxf(acc[nt][3] + bv1 + w01 * x0b + w11 * x1b, 0.f);
                atomicMax(gpa + o * P2,       __float_as_uint(v0));
                atomicMax(gpa + (o + 1) * P2, __float_as_uint(v1));
                atomicMax(gpb + o * P2,       __float_as_uint(v2));
                atomicMax(gpb + (o + 1) * P2, __float_as_uint(v3));
                if (put0) { d_fcol0[br * 128 + o] = v0; d_fcol0[br * 128 + o + 1] = v1; }
            }
        }
        __syncthreads();
    }
}

// ---------------- K5: empty-cluster fallback ----------------
__global__ void k_fix() {
    int idx = blockIdx.x * 256 + threadIdx.x;
    int m = idx & 63; int c = (idx >> 6) & 127; int br = idx >> 13;
    int b = br >> 2;
    if (d_ccnt[b * Mv + m] == 0.f)
        d_g[(2 + c) * P2 + br * Mv + m] = d_fcol0[br * 128 + c];
}

// ---------------- gp GEMM + bias + ReLU (warp-uniform FFMA2) --------------
__global__ void __launch_bounds__(256) k_gemm(
    const float* __restrict__ W, const float* __restrict__ bias,
    const float* __restrict__ in1, int C1,
    const float* __restrict__ in2, int C2,
    float* __restrict__ out, int P)
{
    __shared__ __align__(16) float Wsh[16][68];
    __shared__ __align__(16) float Ish[16][68];
    const int C = C1 + C2;
    const int col0 = blockIdx.x * 64, ob0 = blockIdx.y * 64;
    const int tid = threadIdx.x;
    const int og = tid >> 5;
    const int cg = tid & 31;
    const int o0 = og * 8, p0 = cg * 2;
    unsigned long long acc[8];
    #pragma unroll
    for (int i = 0; i < 8; i++) acc[i] = 0ull;

    for (int k0 = 0; k0 < C; k0 += 16) {
        #pragma unroll
        for (int q = 0; q < 4; q++) {
            int l = tid * 4 + q; int oo = l >> 4, kk = l & 15;
            int c = k0 + kk;
            Wsh[kk][oo] = (c < C) ? W[(ob0 + oo) * C + c] : 0.f;
        }
        #pragma unroll
        for (int q = 0; q < 4; q++) {
            int l = tid * 4 + q; int kk = l >> 6, cc = l & 63;
            int c = k0 + kk;
            float v = 0.f;
            if (c < C1)      v = in1[c * P + col0 + cc];
            else if (c < C)  v = in2[(c - C1) * P + col0 + cc];
            Ish[kk][cc] = v;
        }
        __syncthreads();
        #pragma unroll
        for (int kk = 0; kk < 16; kk++) {
            float4 wA = *(const float4*)&Wsh[kk][o0];
            float4 wB = *(const float4*)&Wsh[kk][o0 + 4];
            unsigned long long a = *(const unsigned long long*)&Ish[kk][p0];
            acc[0] = ffma2(pack2(wA.x, wA.x), a, acc[0]);
            acc[1] = ffma2(pack2(wA.y, wA.y), a, acc[1]);
            acc[2] = ffma2(pack2(wA.z, wA.z), a, acc[2]);
            acc[3] = ffma2(pack2(wA.w, wA.w), a, acc[3]);
            acc[4] = ffma2(pack2(wB.x, wB.x), a, acc[4]);
            acc[5] = ffma2(pack2(wB.y, wB.y), a, acc[5]);
            acc[6] = ffma2(pack2(wB.z, wB.z), a, acc[6]);
            acc[7] = ffma2(pack2(wB.w, wB.w), a, acc[7]);
        }
        __syncthreads();
    }
    #pragma unroll
    for (int i = 0; i < 8; i++) {
        int o = ob0 + o0 + i;
        float bv = bias[o];
        float vl = fmaxf(lo2(acc[i]) + bv, 0.f);
        float vh = fmaxf(hi2(acc[i]) + bv, 0.f);
        *(float2*)&out[o * P + col0 + p0] = make_float2(vl, vh);
    }
}

// ---------------- K6: final max over (r, m) ----------------
__global__ void k_reduce(float* __restrict__ out) {
    int idx = blockIdx.x * 256 + threadIdx.x;
    int b = idx >> 9, f = idx & 511;
    const float* src = &d_D2[f * P2 + b * 256];
    float v = 0.f;
    #pragma unroll 8
    for (int j = 0; j < 256; j++) v = fmaxf(v, src[j]);
    out[b * Fv + f] = v;
}

// ---------------- host launcher ----------------
extern "C" void kernel_launch(void* const* d_in, const int* in_sizes, int n_in,
                              void* d_out, int out_size) {
    const float* x    = (const float*)d_in[0];
    const float* node = (const float*)d_in[2];
    const float* fpW0 = (const float*)d_in[4];  const float* fpb0 = (const float*)d_in[5];
    const float* fpW1 = (const float*)d_in[6];  const float* fpb1 = (const float*)d_in[7];
    const float* fpW2 = (const float*)d_in[8];  const float* fpb2 = (const float*)d_in[9];
    const float* fpW3 = (const float*)d_in[10]; const float* fpb3 = (const float*)d_in[11];
    const float* gpW0 = (const float*)d_in[12]; const float* gpb0 = (const float*)d_in[13];
    const float* gpW1 = (const float*)d_in[14]; const float* gpb1 = (const float*)d_in[15];
    const float* gpW2 = (const float*)d_in[16]; const float* gpb2 = (const float*)d_in[17];
    const float* gpW3 = (const float*)d_in[18]; const float* gpb3 = (const float*)d_in[19];

    float *p_g, *p_A, *p_B2, *p_C2, *p_D2;
    cudaGetSymbolAddress((void**)&p_g,  d_g);
    cudaGetSymbolAddress((void**)&p_A,  d_A);
    cudaGetSymbolAddress((void**)&p_B2, d_B2);
    cudaGetSymbolAddress((void**)&p_C2, d_C2);
    cudaGetSymbolAddress((void**)&p_D2, d_D2);

    cudaFuncSetAttribute(k_fp_mma, cudaFuncAttributeMaxDynamicSharedMemorySize, SMEM_TC);

    k_init<<<(130 * P2 + 255) / 256, 256>>>();
    k_topk<<<(Bv * Nv) / 256, 256>>>(x, node);
    k_nodes<<<1, 256>>>();

    k_fp_mma<<<148, 512, SMEM_TC>>>(x, fpW0, fpb0, fpW1, fpb1,
                                    fpW2, fpb2, fpW3, fpb3);
    k_fix<<<(BRv * 128 * Mv) / 256, 256>>>();

    k_gemm<<<dim3(P2 / 64, 4), 256>>>(gpW0, gpb0, p_g,  130, nullptr, 0,   p_A,  P2);
    k_gemm<<<dim3(P2 / 64, 4), 256>>>(gpW1, gpb1, p_A,  256, nullptr, 0,   p_B2, P2);
    k_gemm<<<dim3(P2 / 64, 8), 256>>>(gpW2, gpb2, p_B2, 256, nullptr, 0,   p_C2, P2);
    k_gemm<<<dim3(P2 / 64, 8), 256>>>(gpW3, gpb3, p_g,  130, p_C2,  512,   p_D2, P2);

    k_reduce<<<(Bv * Fv) / 256, 256>>>((float*)d_out);
}

// round 10
// speedup vs baseline: 1.2238x; 1.0870x over previous
#include <cuda_runtime.h>
#include <cuda_bf16.h>
#include <math.h>
#include <stdint.h>

// ---------------- problem constants ----------------
#define Bv   4
#define Rv   4
#define Nv   4096
#define Mv   64
#define KNv  12288
#define BRv  16
#define P1   196608
#define P2   1024
#define Fv   512
#define TILES2 1536          // P1 / 128
#define TPB2   96            // KN / 128 tiles per br

// ---------------- device scratch ----------------
__device__ int   d_topk[Bv * Nv * 3];
__device__ float d_csum[Bv * 2 * Mv];
__device__ float d_ccnt[Bv * Mv];
__device__ float d_nrot[BRv * 2 * Mv];
__device__ float d_g[130 * P2];
__device__ float d_fcol0[BRv * 128];
__device__ float d_A[256 * P2];
__device__ float d_B2[256 * P2];
__device__ float d_C2[512 * P2];
__device__ float d_D2[512 * P2];

// ---------------- scalar helpers ----------------
__device__ __forceinline__ unsigned long long ffma2(unsigned long long a,
                                                    unsigned long long b,
                                                    unsigned long long c) {
    unsigned long long d;
    asm("fma.rn.f32x2 %0, %1, %2, %3;" : "=l"(d) : "l"(a), "l"(b), "l"(c));
    return d;
}
__device__ __forceinline__ unsigned long long pack2(float lo, float hi) {
    unsigned long long r;
    asm("mov.b64 %0, {%1, %2};" : "=l"(r) : "f"(lo), "f"(hi));
    return r;
}
__device__ __forceinline__ float lo2(unsigned long long a) { return __uint_as_float((unsigned)a); }
__device__ __forceinline__ float hi2(unsigned long long a) { return __uint_as_float((unsigned)(a >> 32)); }

__device__ __forceinline__ void rot_cs(int r, float& c, float& s) {
    float th = 6.2831855f * (float)r * 0.25f;
    c = cosf(th);
    s = sinf(th);
}
__device__ __forceinline__ uint32_t smem_u32(const void* p) {
    uint32_t a;
    asm("{ .reg .u64 t; cvta.to.shared.u64 t, %1; cvt.u32.u64 %0, t; }" : "=r"(a) : "l"(p));
    return a;
}
__device__ __forceinline__ uint32_t swz(uint32_t b) { return b ^ ((b >> 3) & 0x70); }

// ---------------- warp MMA helpers ----------------
__device__ __forceinline__ void ldsm4(uint32_t* r, uint32_t addr) {
    asm volatile("ldmatrix.sync.aligned.m8n8.x4.shared.b16 {%0,%1,%2,%3}, [%4];"
                 : "=r"(r[0]), "=r"(r[1]), "=r"(r[2]), "=r"(r[3]) : "r"(addr));
}
__device__ __forceinline__ void mma16816(float* d, const uint32_t* a, const uint32_t* b) {
    asm volatile("mma.sync.aligned.m16n8k16.row.col.f32.bf16.bf16.f32 "
                 "{%0,%1,%2,%3}, {%4,%5,%6,%7}, {%8,%9}, {%0,%1,%2,%3};"
                 : "+f"(d[0]), "+f"(d[1]), "+f"(d[2]), "+f"(d[3])
                 : "r"(a[0]), "r"(a[1]), "r"(a[2]), "r"(a[3]), "r"(b[0]), "r"(b[1]));
}

// FUSED hi/lo 3-combo pass: each fragment loaded ONCE from smem,
// 12 MMAs per 32-col group (acc reuse distance 4).
template<int NT>
__device__ __forceinline__ void mma3(float acc[][4], uint32_t aHb, uint32_t aLb,
                                     uint32_t wHb, uint32_t wLb, int mt, int n0, int lane) {
    const int arow = 16 * mt + (lane & 7) + ((lane >> 3) & 1) * 8;
    const int aoff = ((lane >> 4) & 1) * 16;
    const int brow = (lane & 7) + (lane >> 4) * 8;
    const int boff = ((lane >> 3) & 1) * 16;
    #pragma unroll
    for (int ks = 0; ks < 4; ks++) {
        uint32_t aH[4], aL[4];
        uint32_t aoffs = swz((uint32_t)(arow * 128 + 32 * ks + aoff));
        ldsm4(aH, aHb + aoffs);
        ldsm4(aL, aLb + aoffs);
        #pragma unroll
        for (int tph = 0; tph < NT / 4; tph++) {
            int r0 = n0 + 32 * tph + brow;
            uint32_t o0s = swz((uint32_t)(r0 * 128 + 32 * ks + boff));
            uint32_t o1s = swz((uint32_t)((r0 + 16) * 128 + 32 * ks + boff));
            uint32_t wh0[4], wh1[4], wl0[4], wl1[4];
            ldsm4(wh0, wHb + o0s);
            ldsm4(wh1, wHb + o1s);
            ldsm4(wl0, wLb + o0s);
            ldsm4(wl1, wLb + o1s);
            float* a0 = acc[4 * tph + 0];
            float* a1 = acc[4 * tph + 1];
            float* a2 = acc[4 * tph + 2];
            float* a3 = acc[4 * tph + 3];
            mma16816(a0, aH, wh0); mma16816(a1, aH, wh0 + 2);
            mma16816(a2, aH, wh1); mma16816(a3, aH, wh1 + 2);
            mma16816(a0, aH, wl0); mma16816(a1, aH, wl0 + 2);
            mma16816(a2, aH, wl1); mma16816(a3, aH, wl1 + 2);
            mma16816(a0, aL, wh0); mma16816(a1, aL, wh0 + 2);
            mma16816(a2, aL, wh1); mma16816(a3, aL, wh1 + 2);
        }
    }
}

// store bf16 hi/lo pair (cols o, o+1) at point row p
__device__ __forceinline__ void st_pair(uint32_t hB, uint32_t lB, int p, int o,
                                        float v0, float v1) {
    uint32_t h, l;
    asm("cvt.rn.bf16x2.f32 %0, %1, %2;" : "=r"(h) : "f"(v1), "f"(v0));
    float h0 = __uint_as_float(h << 16);
    float h1 = __uint_as_float(h & 0xffff0000u);
    asm("cvt.rn.bf16x2.f32 %0, %1, %2;" : "=r"(l) : "f"(v1 - h1), "f"(v0 - h0));
    uint32_t off = swz((uint32_t)(p * 128 + 2 * o));
    asm volatile("st.shared.b32 [%0], %1;" :: "r"(hB + off), "r"(h) : "memory");
    asm volatile("st.shared.b32 [%0], %1;" :: "r"(lB + off), "r"(l) : "memory");
}

// pack 8 fp32 -> 16B bf16-hi + 16B bf16-lo (for L0)
__device__ __forceinline__ void pack_store8(uint32_t addrH, uint32_t addrL, const float* v) {
    uint32_t h[4], l[4];
    #pragma unroll
    for (int q = 0; q < 4; q++) {
        float a = v[2 * q], b = v[2 * q + 1];
        asm("cvt.rn.bf16x2.f32 %0, %1, %2;" : "=r"(h[q]) : "f"(b), "f"(a));
        float ha = __uint_as_float(h[q] << 16);
        float hb = __uint_as_float(h[q] & 0xffff0000u);
        asm("cvt.rn.bf16x2.f32 %0, %1, %2;" : "=r"(l[q]) : "f"(b - hb), "f"(a - ha));
    }
    asm volatile("st.shared.v4.b32 [%0], {%1, %2, %3, %4};"
                 :: "r"(addrH), "r"(h[0]), "r"(h[1]), "r"(h[2]), "r"(h[3]) : "memory");
    asm volatile("st.shared.v4.b32 [%0], {%1, %2, %3, %4};"
                 :: "r"(addrL), "r"(l[0]), "r"(l[1]), "r"(l[2]), "r"(l[3]) : "memory");
}

// ---------------- K0 ----------------
__global__ void k_init() {
    int i = blockIdx.x * 256 + threadIdx.x;
    if (i < Bv * 2 * Mv) d_csum[i] = 0.f;
    if (i < Bv * Mv)     d_ccnt[i] = 0.f;
    if (i < 130 * P2)    d_g[i]    = 0.f;
}

// ---------------- K1: top-3 + cluster accumulation ----------
__global__ void k_topk(const float* __restrict__ x, const float* __restrict__ node) {
    int idx = blockIdx.x * 256 + threadIdx.x;
    if (idx >= Bv * Nv) return;
    int b = idx >> 12, n = idx & (Nv - 1);
    float x0 = x[b * 2 * Nv + n];
    float x1 = x[b * 2 * Nv + Nv + n];
    float d0 = 3.4e38f, d1 = 3.4e38f, d2 = 3.4e38f;
    int   i0 = 0, i1 = 0, i2 = 0;
    #pragma unroll
    for (int m = 0; m < Mv; m++) {
        float dx = x0 - __ldg(&node[b * 2 * Mv + m]);
        float dy = x1 - __ldg(&node[b * 2 * Mv + Mv + m]);
        float d = dx * dx + dy * dy;
        if (d < d0)      { d2 = d1; i2 = i1; d1 = d0; i1 = i0; d0 = d; i0 = m; }
        else if (d < d1) { d2 = d1; i2 = i1; d1 = d;  i1 = m; }
        else if (d < d2) { d2 = d;  i2 = m; }
    }
    int o = idx * 3;
    d_topk[o] = i0; d_topk[o + 1] = i1; d_topk[o + 2] = i2;
    atomicAdd(&d_csum[b * 2 * Mv + i0],      x0);
    atomicAdd(&d_csum[b * 2 * Mv + Mv + i0], x1);
    atomicAdd(&d_ccnt[b * Mv + i0], 1.f);
    atomicAdd(&d_csum[b * 2 * Mv + i1],      x0);
    atomicAdd(&d_csum[b * 2 * Mv + Mv + i1], x1);
    atomicAdd(&d_ccnt[b * Mv + i1], 1.f);
    atomicAdd(&d_csum[b * 2 * Mv + i2],      x0);
    atomicAdd(&d_csum[b * 2 * Mv + Mv + i2], x1);
    atomicAdd(&d_ccnt[b * Mv + i2], 1.f);
}

// ---------------- K2 ----------------
__global__ void k_nodes() {
    int idx = threadIdx.x;
    int b = idx >> 6, m = idx & 63;
    float cnt = d_ccnt[b * Mv + m];
    float inv = 1.f / (cnt + 1e-5f);
    float m0 = d_csum[b * 2 * Mv + m]      * inv;
    float m1 = d_csum[b * 2 * Mv + Mv + m] * inv;
    #pragma unroll
    for (int r = 0; r < Rv; r++) {
        float c, s; rot_cs(r, c, s);
        float n0 = c * m0 - s * m1;
        float n1 = s * m0 + c * m1;
        int br = b * Rv + r;
        d_nrot[(br * 2 + 0) * Mv + m] = n0;
        d_nrot[(br * 2 + 1) * Mv + m] = n1;
        d_g[0 * P2 + br * Mv + m] = n0;
        d_g[1 * P2 + br * Mv + m] = n1;
    }
}

// ---------------- warp-MMA fused fp block ----------------
// smem byte offsets (bf16 tiles: [row][64k] = 128B rows, SW128, 1024-aligned)
#define OW1H  0         // W1 hi  [64o][64k]
#define OW1L  8192
#define OW2H  16384     // W2 hi  [128o][64k]
#define OW2L  32768
#define OW3AH 49152     // W3 k=2..65
#define OW3AL 65536
#define OW3BH 81920     // W3 k=66..129
#define OW3BL 98304
#define OBAH  114688    // act tile A (L0 out / L1 in; reused: h3 ch 0-63)
#define OBAL  131072
#define ORH   147456    // act tile R (L1 out / L2 in)
#define ORL   163840
#define OCBH  180224    // h3 ch 64-127
#define OCBL  196608
#define OW0F  212992    // W0 fp32 [128]
#define OW3X  213504    // W3 x-part fp32 [256]
#define OB0   214528
#define OB1   214784
#define OB2   215040
#define OB3   215552
#define OXS   216064    // xdec fp32 [256]
#define OMS   217088    // int [128]
#define SMEM_TC 217600

__global__ void __launch_bounds__(512, 1) k_fp_mma(
    const float* __restrict__ x,
    const float* __restrict__ W0, const float* __restrict__ b0,
    const float* __restrict__ W1, const float* __restrict__ b1,
    const float* __restrict__ W2, const float* __restrict__ b2,
    const float* __restrict__ W3, const float* __restrict__ b3)
{
    extern __shared__ __align__(1024) char smc[];
    float* smf = (float*)smc;
    const int tid  = threadIdx.x;
    const int wid  = tid >> 5;
    const int lane = tid & 31;
    const uint32_t sb = smem_u32(smc);

    // ---- one-time: weights -> bf16 hi/lo swizzled K-major tiles ----
    for (int i = tid; i < 4096; i += 512) {
        int o = i >> 6, k = i & 63;
        float w = W1[o * 64 + k];
        __nv_bfloat16 h = __float2bfloat16(w);
        __nv_bfloat16 l = __float2bfloat16(w - __bfloat162float(h));
        uint32_t off = swz(o * 128 + 2 * k);
        *(__nv_bfloat16*)(smc + OW1H + off) = h;
        *(__nv_bfloat16*)(smc + OW1L + off) = l;
    }
    for (int i = tid; i < 8192; i += 512) {
        int o = i >> 6, k = i & 63;
        float w = W2[o * 64 + k];
        __nv_bfloat16 h = __float2bfloat16(w);
        __nv_bfloat16 l = __float2bfloat16(w - __bfloat162float(h));
        uint32_t off = swz(o * 128 + 2 * k);
        *(__nv_bfloat16*)(smc + OW2H + off) = h;
        *(__nv_bfloat16*)(smc + OW2L + off) = l;
    }
    for (int i = tid; i < 8192; i += 512) {
        int o = i >> 6, k = i & 63;
        float w = W3[o * 130 + 2 + k];
        __nv_bfloat16 h = __float2bfloat16(w);
        __nv_bfloat16 l = __float2bfloat16(w - __bfloat162float(h));
        uint32_t off = swz(o * 128 + 2 * k);
        *(__nv_bfloat16*)(smc + OW3AH + off) = h;
        *(__nv_bfloat16*)(smc + OW3AL + off) = l;
    }
    for (int i = tid; i < 8192; i += 512) {
        int o = i >> 6, k = i & 63;
        float w = W3[o * 130 + 66 + k];
        __nv_bfloat16 h = __float2bfloat16(w);
        __nv_bfloat16 l = __float2bfloat16(w - __bfloat162float(h));
        uint32_t off = swz(o * 128 + 2 * k);
        *(__nv_bfloat16*)(smc + OW3BH + off) = h;
        *(__nv_bfloat16*)(smc + OW3BL + off) = l;
    }
    if (tid < 128) {
        smf[OW0F / 4 + tid] = W0[tid];
        smf[OW3X / 4 + tid]       = W3[tid * 130];
        smf[OW3X / 4 + 128 + tid] = W3[tid * 130 + 1];
        if (tid < 64) { smf[OB0 / 4 + tid] = b0[tid]; smf[OB1 / 4 + tid] = b1[tid]; }
        smf[OB2 / 4 + tid] = b2[tid];
        smf[OB3 / 4 + tid] = b3[tid];
    }
    __syncthreads();

    int* ms = (int*)(smc + OMS);
    const int mt = wid >> 1;          // m-tile 0..7 (16 points each)
    const int nh = wid & 1;           // n-half
    const int g  = lane >> 2;         // 0..7
    const int tq = lane & 3;          // 0..3
    const int rp = 16 * mt + g;       // point row (and rp+8)

    for (int t = blockIdx.x; t < TILES2; t += gridDim.x) {
        int br = t / TPB2; int tloc = t - br * TPB2; int kn0 = tloc * 128;
        int b = br >> 2, r = br & 3;

        // ---- P0: xdec (fp32, exact) ----
        if (tid < 128) {
            int kn = kn0 + tid; int k = kn >> 12; int n = kn & (Nv - 1);
            float x0 = x[b * 2 * Nv + n], x1 = x[b * 2 * Nv + Nv + n];
            float cc, ss; rot_cs(r, cc, ss);
            float xr0 = cc * x0 - ss * x1;
            float xr1 = ss * x0 + cc * x1;
            int m = d_topk[(b * Nv + n) * 3 + k];
            smf[OXS / 4 + tid]       = xr0 - d_nrot[(br * 2 + 0) * Mv + m];
            smf[OXS / 4 + 128 + tid] = xr1 - d_nrot[(br * 2 + 1) * Mv + m];
            ms[tid] = m;
        }
        __syncthreads();

        // ---- L0 scalar (K=2): h1 -> tile A ----
        {
            int pp = tid & 127, q = tid >> 7;
            float x0 = smf[OXS / 4 + pp], x1 = smf[OXS / 4 + 128 + pp];
            float v[16];
            #pragma unroll
            for (int j = 0; j < 16; j++) {
                int o = 16 * q + j;
                v[j] = fmaxf(fmaf(smf[OW0F / 4 + 2 * o], x0,
                             fmaf(smf[OW0F / 4 + 2 * o + 1], x1, smf[OB0 / 4 + o])), 0.f);
            }
            uint32_t ro = pp * 128 + 32 * q;
            pack_store8(sb + OBAH + swz(ro),      sb + OBAL + swz(ro),      v);
            pack_store8(sb + OBAH + swz(ro + 16), sb + OBAL + swz(ro + 16), v + 8);
        }
        __syncthreads();

        // ---- L1: h2 = relu(h1 x W1 + b1), N=64 ----
        {
            float acc[4][4];
            #pragma unroll
            for (int i = 0; i < 4; i++)
                #pragma unroll
                for (int j = 0; j < 4; j++) acc[i][j] = 0.f;
            int n0 = nh * 32;
            mma3<4>(acc, sb + OBAH, sb + OBAL, sb + OW1H, sb + OW1L, mt, n0, lane);
            #pragma unroll
            for (int nt = 0; nt < 4; nt++) {
                int o = n0 + 8 * nt + 2 * tq;
                float bv0 = smf[OB1 / 4 + o], bv1 = smf[OB1 / 4 + o + 1];
                st_pair(sb + ORH, sb + ORL, rp, o,
                        fmaxf(acc[nt][0] + bv0, 0.f), fmaxf(acc[nt][1] + bv1, 0.f));
                st_pair(sb + ORH, sb + ORL, rp + 8, o,
                        fmaxf(acc[nt][2] + bv0, 0.f), fmaxf(acc[nt][3] + bv1, 0.f));
            }
        }
        __syncthreads();

        // ---- L2: h3 = relu(h2 x W2 + b2), N=128 -> tiles A (o<64) / CB ----
        {
            float acc[8][4];
            #pragma unroll
            for (int i = 0; i < 8; i++)
                #pragma unroll
                for (int j = 0; j < 4; j++) acc[i][j] = 0.f;
            int n0 = nh * 64;
            mma3<8>(acc, sb + ORH, sb + ORL, sb + OW2H, sb + OW2L, mt, n0, lane);
            uint32_t hB = nh ? (sb + OCBH) : (sb + OBAH);
            uint32_t lB = nh ? (sb + OCBL) : (sb + OBAL);
            #pragma unroll
            for (int nt = 0; nt < 8; nt++) {
                int o = n0 + 8 * nt + 2 * tq;
                float bv0 = smf[OB2 / 4 + o], bv1 = smf[OB2 / 4 + o + 1];
                int oc = o & 63;
                st_pair(hB, lB, rp, oc,
                        fmaxf(acc[nt][0] + bv0, 0.f), fmaxf(acc[nt][1] + bv1, 0.f));
                st_pair(hB, lB, rp + 8, oc,
                        fmaxf(acc[nt][2] + bv0, 0.f), fmaxf(acc[nt][3] + bv1, 0.f));
            }
        }
        __syncthreads();

        // ---- L3: feat = relu(concat(x,h3) x W3 + b3), N=128 -> scatter-max ----
        {
            float acc[8][4];
            #pragma unroll
            for (int i = 0; i < 8; i++)
                #pragma unroll
                for (int j = 0; j < 4; j++) acc[i][j] = 0.f;
            int n0 = nh * 64;
            mma3<8>(acc, sb + OBAH, sb + OBAL, sb + OW3AH, sb + OW3AL, mt, n0, lane);
            mma3<8>(acc, sb + OCBH, sb + OCBL, sb + OW3BH, sb + OW3BL, mt, n0, lane);

            float x0a = smf[OXS / 4 + rp],     x1a = smf[OXS / 4 + 128 + rp];
            float x0b = smf[OXS / 4 + rp + 8], x1b = smf[OXS / 4 + 128 + rp + 8];
            int ma = ms[rp], mb = ms[rp + 8];
            unsigned* gpa = (unsigned*)&d_g[2 * P2 + br * Mv + ma];
            unsigned* gpb = (unsigned*)&d_g[2 * P2 + br * Mv + mb];
            bool put0 = (tloc == 0 && rp == 0);
            #pragma unroll
            for (int nt = 0; nt < 8; nt++) {
                int o = n0 + 8 * nt + 2 * tq;
                float w00 = smf[OW3X / 4 + o],       w10 = smf[OW3X / 4 + 128 + o];
                float w01 = smf[OW3X / 4 + o + 1],   w11 = smf[OW3X / 4 + 128 + o + 1];
                float bv0 = smf[OB3 / 4 + o],        bv1 = smf[OB3 / 4 + o + 1];
                float v0 = fmaxf(acc[nt][0] + bv0 + w00 * x0a + w10 * x1a, 0.f);
                float v1 = fmaxf(acc[nt][1] + bv1 + w01 * x0a + w11 * x1a, 0.f);
                float v2 = fmaxf(acc[nt][2] + bv0 + w00 * x0b + w10 * x1b, 0.f);
                float v3 = fmaxf(acc[nt][3] + bv1 + w01 * x0b + w11 * x1b, 0.f);
                atomicMax(gpa + o * P2,       __float_as_uint(v0));
                atomicMax(gpa + (o + 1) * P2, __float_as_uint(v1));
                atomicMax(gpb + o * P2,       __float_as_uint(v2));
                atomicMax(gpb + (o + 1) * P2, __float_as_uint(v3));
                if (put0) { d_fcol0[br * 128 + o] = v0; d_fcol0[br * 128 + o + 1] = v1; }
            }
        }
        __syncthreads();
    }
}

// ---------------- K5: empty-cluster fallback ----------------
__global__ void k_fix() {
    int idx = blockIdx.x * 256 + threadIdx.x;
    int m = idx & 63; int c = (idx >> 6) & 127; int br = idx >> 13;
    int b = br >> 2;
    if (d_ccnt[b * Mv + m] == 0.f)
        d_g[(2 + c) * P2 + br * Mv + m] = d_fcol0[br * 128 + c];
}

// ---------------- gp GEMM + bias + ReLU (warp-uniform FFMA2) --------------
__global__ void __launch_bounds__(256) k_gemm(
    const float* __restrict__ W, const float* __restrict__ bias,
    const float* __restrict__ in1, int C1,
    const float* __restrict__ in2, int C2,
    float* __restrict__ out, int P)
{
    __shared__ __align__(16) float Wsh[16][68];
    __shared__ __align__(16) float Ish[16][68];
    const int C = C1 + C2;
    const int col0 = blockIdx.x * 64, ob0 = blockIdx.y * 64;
    const int tid = threadIdx.x;
    const int og = tid >> 5;
    const int cg = tid & 31;
    const int o0 = og * 8, p0 = cg * 2;
    unsigned long long acc[8];
    #pragma unroll
    for (int i = 0; i < 8; i++) acc[i] = 0ull;

    for (int k0 = 0; k0 < C; k0 += 16) {
        #pragma unroll
        for (int q = 0; q < 4; q++) {
            int l = tid * 4 + q; int oo = l >> 4, kk = l & 15;
            int c = k0 + kk;
            Wsh[kk][oo] = (c < C) ? W[(ob0 + oo) * C + c] : 0.f;
        }
        #pragma unroll
        for (int q = 0; q < 4; q++) {
            int l = tid * 4 + q; int kk = l >> 6, cc = l & 63;
            int c = k0 + kk;
            float v = 0.f;
            if (c < C1)      v = in1[c * P + col0 + cc];
            else if (c < C)  v = in2[(c - C1) * P + col0 + cc];
            Ish[kk][cc] = v;
        }
        __syncthreads();
        #pragma unroll
        for (int kk = 0; kk < 16; kk++) {
            float4 wA = *(const float4*)&Wsh[kk][o0];
            float4 wB = *(const float4*)&Wsh[kk][o0 + 4];
            unsigned long long a = *(const unsigned long long*)&Ish[kk][p0];
            acc[0] = ffma2(pack2(wA.x, wA.x), a, acc[0]);
            acc[1] = ffma2(pack2(wA.y, wA.y), a, acc[1]);
            acc[2] = ffma2(pack2(wA.z, wA.z), a, acc[2]);
            acc[3] = ffma2(pack2(wA.w, wA.w), a, acc[3]);
            acc[4] = ffma2(pack2(wB.x, wB.x), a, acc[4]);
            acc[5] = ffma2(pack2(wB.y, wB.y), a, acc[5]);
            acc[6] = ffma2(pack2(wB.z, wB.z), a, acc[6]);
            acc[7] = ffma2(pack2(wB.w, wB.w), a, acc[7]);
        }
        __syncthreads();
    }
    #pragma unroll
    for (int i = 0; i < 8; i++) {
        int o = ob0 + o0 + i;
        float bv = bias[o];
        float vl = fmaxf(lo2(acc[i]) + bv, 0.f);
        float vh = fmaxf(hi2(acc[i]) + bv, 0.f);
        *(float2*)&out[o * P + col0 + p0] = make_float2(vl, vh);
    }
}

// ---------------- K6: final max over (r, m) ----------------
__global__ void k_reduce(float* __restrict__ out) {
    int idx = blockIdx.x * 256 + threadIdx.x;
    int b = idx >> 9, f = idx & 511;
    const float* src = &d_D2[f * P2 + b * 256];
    float v = 0.f;
    #pragma unroll 8
    for (int j = 0; j < 256; j++) v = fmaxf(v, src[j]);
    out[b * Fv + f] = v;
}

// ---------------- host launcher ----------------
extern "C" void kernel_launch(void* const* d_in, const int* in_sizes, int n_in,
                              void* d_out, int out_size) {
    const float* x    = (const float*)d_in[0];
    const float* node = (const float*)d_in[2];
    const float* fpW0 = (const float*)d_in[4];  const float* fpb0 = (const float*)d_in[5];
    const float* fpW1 = (const float*)d_in[6];  const float* fpb1 = (const float*)d_in[7];
    const float* fpW2 = (const float*)d_in[8];  const float* fpb2 = (const float*)d_in[9];
    const float* fpW3 = (const float*)d_in[10]; const float* fpb3 = (const float*)d_in[11];
    const float* gpW0 = (const float*)d_in[12]; const float* gpb0 = (const float*)d_in[13];
    const float* gpW1 = (const float*)d_in[14]; const float* gpb1 = (const float*)d_in[15];
    const float* gpW2 = (const float*)d_in[16]; const float* gpb2 = (const float*)d_in[17];
    const float* gpW3 = (const float*)d_in[18]; const float* gpb3 = (const float*)d_in[19];

    float *p_g, *p_A, *p_B2, *p_C2, *p_D2;
    cudaGetSymbolAddress((void**)&p_g,  d_g);
    cudaGetSymbolAddress((void**)&p_A,  d_A);
    cudaGetSymbolAddress((void**)&p_B2, d_B2);
    cudaGetSymbolAddress((void**)&p_C2, d_C2);
    cudaGetSymbolAddress((void**)&p_D2, d_D2);

    cudaFuncSetAttribute(k_fp_mma, cudaFuncAttributeMaxDynamicSharedMemorySize, SMEM_TC);

    k_init<<<(130 * P2 + 255) / 256, 256>>>();
    k_topk<<<(Bv * Nv) / 256, 256>>>(x, node);
    k_nodes<<<1, 256>>>();

    k_fp_mma<<<148, 512, SMEM_TC>>>(x, fpW0, fpb0, fpW1, fpb1,
                                    fpW2, fpb2, fpW3, fpb3);
    k_fix<<<(BRv * 128 * Mv) / 256, 256>>>();

    k_gemm<<<dim3(P2 / 64, 4), 256>>>(gpW0, gpb0, p_g,  130, nullptr, 0,   p_A,  P2);
    k_gemm<<<dim3(P2 / 64, 4), 256>>>(gpW1, gpb1, p_A,  256, nullptr, 0,   p_B2, P2);
    k_gemm<<<dim3(P2 / 64, 8), 256>>>(gpW2, gpb2, p_B2, 256, nullptr, 0,   p_C2, P2);
    k_gemm<<<dim3(P2 / 64, 8), 256>>>(gpW3, gpb3, p_g,  130, p_C2,  512,   p_D2, P2);

    k_reduce<<<(Bv * Fv) / 256, 256>>>((float*)d_out);
}

// round 11
// speedup vs baseline: 1.2325x; 1.0071x over previous
#include <cuda_runtime.h>
#include <cuda_bf16.h>
#include <math.h>
#include <stdint.h>

// ---------------- problem constants ----------------
#define Bv   4
#define Rv   4
#define Nv   4096
#define Mv   64
#define KNv  12288
#define BRv  16
#define P1   196608
#define P2   1024
#define Fv   512
#define TILES64 3072         // P1 / 64
#define TPB64   192          // KN / 64

// ---------------- device scratch ----------------
__device__ int   d_topk[Bv * Nv * 3];
__device__ float d_csum[Bv * 2 * Mv];
__device__ float d_ccnt[Bv * Mv];
__device__ float d_nrot[BRv * 2 * Mv];
__device__ float d_g[130 * P2];
__device__ float d_fcol0[BRv * 128];
__device__ float d_A[256 * P2];
__device__ float d_B2[256 * P2];
__device__ float d_C2[512 * P2];
__device__ float d_D2[512 * P2];

// ---------------- scalar helpers ----------------
__device__ __forceinline__ unsigned long long ffma2(unsigned long long a,
                                                    unsigned long long b,
                                                    unsigned long long c) {
    unsigned long long d;
    asm("fma.rn.f32x2 %0, %1, %2, %3;" : "=l"(d) : "l"(a), "l"(b), "l"(c));
    return d;
}
__device__ __forceinline__ unsigned long long pack2(float lo, float hi) {
    unsigned long long r;
    asm("mov.b64 %0, {%1, %2};" : "=l"(r) : "f"(lo), "f"(hi));
    return r;
}
__device__ __forceinline__ float lo2(unsigned long long a) { return __uint_as_float((unsigned)a); }
__device__ __forceinline__ float hi2(unsigned long long a) { return __uint_as_float((unsigned)(a >> 32)); }

__device__ __forceinline__ void rot_cs(int r, float& c, float& s) {
    float th = 6.2831855f * (float)r * 0.25f;
    c = cosf(th);
    s = sinf(th);
}
__device__ __forceinline__ uint32_t smem_u32(const void* p) {
    uint32_t a;
    asm("{ .reg .u64 t; cvta.to.shared.u64 t, %1; cvt.u32.u64 %0, t; }" : "=r"(a) : "l"(p));
    return a;
}
__device__ __forceinline__ uint32_t swz(uint32_t b) { return b ^ ((b >> 3) & 0x70); }

// ---------------- warp MMA helpers ----------------
__device__ __forceinline__ void ldsm4(uint32_t* r, uint32_t addr) {
    asm volatile("ldmatrix.sync.aligned.m8n8.x4.shared.b16 {%0,%1,%2,%3}, [%4];"
                 : "=r"(r[0]), "=r"(r[1]), "=r"(r[2]), "=r"(r[3]) : "r"(addr));
}
__device__ __forceinline__ void mma16816(float* d, const uint32_t* a, const uint32_t* b) {
    asm volatile("mma.sync.aligned.m16n8k16.row.col.f32.bf16.bf16.f32 "
                 "{%0,%1,%2,%3}, {%4,%5,%6,%7}, {%8,%9}, {%0,%1,%2,%3};"
                 : "+f"(d[0]), "+f"(d[1]), "+f"(d[2]), "+f"(d[3])
                 : "r"(a[0]), "r"(a[1]), "r"(a[2]), "r"(a[3]), "r"(b[0]), "r"(b[1]));
}

// hi/lo 3-combo pass, combo-grouped for max acc ILP (same-acc distance = NT).
// Weight-register live range kept at 16 regs: hi weights used by combos 1+3,
// lo weights loaded afterwards.
template<int NT>
__device__ __forceinline__ void mma3(float acc[][4], uint32_t aHb, uint32_t aLb,
                                     uint32_t wHb, uint32_t wLb, int mt, int n0, int lane) {
    const int arow = 16 * mt + (lane & 7) + ((lane >> 3) & 1) * 8;
    const int aoff = ((lane >> 4) & 1) * 16;
    const int brow = (lane & 7) + (lane >> 4) * 8;
    const int boff = ((lane >> 3) & 1) * 16;
    #pragma unroll
    for (int ks = 0; ks < 4; ks++) {
        uint32_t aH[4], aL[4];
        uint32_t aoffs = swz((uint32_t)(arow * 128 + 32 * ks + aoff));
        ldsm4(aH, aHb + aoffs);
        ldsm4(aL, aLb + aoffs);
        uint32_t roffs[NT / 2];
        uint32_t wfr[NT / 2][4];
        #pragma unroll
        for (int u = 0; u < NT / 2; u++) {
            roffs[u] = swz((uint32_t)((n0 + 16 * u + brow) * 128 + 32 * ks + boff));
            ldsm4(wfr[u], wHb + roffs[u]);
        }
        #pragma unroll
        for (int u = 0; u < NT / 2; u++) {       // Ah x Wh
            mma16816(acc[2 * u], aH, wfr[u]); mma16816(acc[2 * u + 1], aH, wfr[u] + 2);
        }
        #pragma unroll
        for (int u = 0; u < NT / 2; u++) {       // Al x Wh
            mma16816(acc[2 * u], aL, wfr[u]); mma16816(acc[2 * u + 1], aL, wfr[u] + 2);
        }
        #pragma unroll
        for (int u = 0; u < NT / 2; u++)
            ldsm4(wfr[u], wLb + roffs[u]);
        #pragma unroll
        for (int u = 0; u < NT / 2; u++) {       // Ah x Wl
            mma16816(acc[2 * u], aH, wfr[u]); mma16816(acc[2 * u + 1], aH, wfr[u] + 2);
        }
    }
}

// store bf16 hi/lo pair (cols o, o+1) at point row p
__device__ __forceinline__ void st_pair(uint32_t hB, uint32_t lB, int p, int o,
                                        float v0, float v1) {
    uint32_t h, l;
    asm("cvt.rn.bf16x2.f32 %0, %1, %2;" : "=r"(h) : "f"(v1), "f"(v0));
    float h0 = __uint_as_float(h << 16);
    float h1 = __uint_as_float(h & 0xffff0000u);
    asm("cvt.rn.bf16x2.f32 %0, %1, %2;" : "=r"(l) : "f"(v1 - h1), "f"(v0 - h0));
    uint32_t off = swz((uint32_t)(p * 128 + 2 * o));
    asm volatile("st.shared.b32 [%0], %1;" :: "r"(hB + off), "r"(h) : "memory");
    asm volatile("st.shared.b32 [%0], %1;" :: "r"(lB + off), "r"(l) : "memory");
}

// pack 8 fp32 -> 16B bf16-hi + 16B bf16-lo (for L0)
__device__ __forceinline__ void pack_store8(uint32_t addrH, uint32_t addrL, const float* v) {
    uint32_t h[4], l[4];
    #pragma unroll
    for (int q = 0; q < 4; q++) {
        float a = v[2 * q], b = v[2 * q + 1];
        asm("cvt.rn.bf16x2.f32 %0, %1, %2;" : "=r"(h[q]) : "f"(b), "f"(a));
        float ha = __uint_as_float(h[q] << 16);
        float hb = __uint_as_float(h[q] & 0xffff0000u);
        asm("cvt.rn.bf16x2.f32 %0, %1, %2;" : "=r"(l[q]) : "f"(b - hb), "f"(a - ha));
    }
    asm volatile("st.shared.v4.b32 [%0], {%1, %2, %3, %4};"
                 :: "r"(addrH), "r"(h[0]), "r"(h[1]), "r"(h[2]), "r"(h[3]) : "memory");
    asm volatile("st.shared.v4.b32 [%0], {%1, %2, %3, %4};"
                 :: "r"(addrL), "r"(l[0]), "r"(l[1]), "r"(l[2]), "r"(l[3]) : "memory");
}

// ---------------- K0 ----------------
__global__ void k_init() {
    int i = blockIdx.x * 256 + threadIdx.x;
    if (i < Bv * 2 * Mv) d_csum[i] = 0.f;
    if (i < Bv * Mv)     d_ccnt[i] = 0.f;
    if (i < 130 * P2)    d_g[i]    = 0.f;
}

// ---------------- K1: top-3 + cluster accumulation ----------
__global__ void k_topk(const float* __restrict__ x, const float* __restrict__ node) {
    int idx = blockIdx.x * 256 + threadIdx.x;
    if (idx >= Bv * Nv) return;
    int b = idx >> 12, n = idx & (Nv - 1);
    float x0 = x[b * 2 * Nv + n];
    float x1 = x[b * 2 * Nv + Nv + n];
    float d0 = 3.4e38f, d1 = 3.4e38f, d2 = 3.4e38f;
    int   i0 = 0, i1 = 0, i2 = 0;
    #pragma unroll
    for (int m = 0; m < Mv; m++) {
        float dx = x0 - __ldg(&node[b * 2 * Mv + m]);
        float dy = x1 - __ldg(&node[b * 2 * Mv + Mv + m]);
        float d = dx * dx + dy * dy;
        if (d < d0)      { d2 = d1; i2 = i1; d1 = d0; i1 = i0; d0 = d; i0 = m; }
        else if (d < d1) { d2 = d1; i2 = i1; d1 = d;  i1 = m; }
        else if (d < d2) { d2 = d;  i2 = m; }
    }
    int o = idx * 3;
    d_topk[o] = i0; d_topk[o + 1] = i1; d_topk[o + 2] = i2;
    atomicAdd(&d_csum[b * 2 * Mv + i0],      x0);
    atomicAdd(&d_csum[b * 2 * Mv + Mv + i0], x1);
    atomicAdd(&d_ccnt[b * Mv + i0], 1.f);
    atomicAdd(&d_csum[b * 2 * Mv + i1],      x0);
    atomicAdd(&d_csum[b * 2 * Mv + Mv + i1], x1);
    atomicAdd(&d_ccnt[b * Mv + i1], 1.f);
    atomicAdd(&d_csum[b * 2 * Mv + i2],      x0);
    atomicAdd(&d_csum[b * 2 * Mv + Mv + i2], x1);
    atomicAdd(&d_ccnt[b * Mv + i2], 1.f);
}

// ---------------- K2 ----------------
__global__ void k_nodes() {
    int idx = threadIdx.x;
    int b = idx >> 6, m = idx & 63;
    float cnt = d_ccnt[b * Mv + m];
    float inv = 1.f / (cnt + 1e-5f);
    float m0 = d_csum[b * 2 * Mv + m]      * inv;
    float m1 = d_csum[b * 2 * Mv + Mv + m] * inv;
    #pragma unroll
    for (int r = 0; r < Rv; r++) {
        float c, s; rot_cs(r, c, s);
        float n0 = c * m0 - s * m1;
        float n1 = s * m0 + c * m1;
        int br = b * Rv + r;
        d_nrot[(br * 2 + 0) * Mv + m] = n0;
        d_nrot[(br * 2 + 1) * Mv + m] = n1;
        d_g[0 * P2 + br * Mv + m] = n0;
        d_g[1 * P2 + br * Mv + m] = n1;
    }
}

// ---------------- warp-MMA fused fp block (2 independent 8-warp groups) ----
// smem byte offsets
#define OW1H  0         // W1 hi  [64o][64k]
#define OW1L  8192
#define OW2H  16384     // W2 hi  [128o][64k]
#define OW2L  32768
#define OW3AH 49152     // W3 k=2..65
#define OW3AL 65536
#define OW3BH 81920     // W3 k=66..129
#define OW3BL 98304
#define OGRP  114688    // group act buffers: 2 x 48KB (A h/l, R h/l, CB h/l, 8KB each)
#define OW0F  212992    // W0 fp32 [128]
#define OW3X  213504    // W3 x-part fp32 [256]
#define OB0   214528
#define OB1   214784
#define OB2   215040
#define OB3   215552
#define OXS   216064    // per-group xdec fp32 [128] : g0 @216064, g1 @216576
#define OMS   217088    // per-group int [64] : g0 @217088, g1 @217344
#define SMEM_TC 217600

__global__ void __launch_bounds__(512, 1) k_fp_mma(
    const float* __restrict__ x,
    const float* __restrict__ W0, const float* __restrict__ b0,
    const float* __restrict__ W1, const float* __restrict__ b1,
    const float* __restrict__ W2, const float* __restrict__ b2,
    const float* __restrict__ W3, const float* __restrict__ b3)
{
    extern __shared__ __align__(1024) char smc[];
    float* smf = (float*)smc;
    const int tid  = threadIdx.x;
    const int wid  = tid >> 5;
    const int lane = tid & 31;
    const uint32_t sb = smem_u32(smc);

    // ---- one-time: weights -> bf16 hi/lo swizzled K-major tiles ----
    for (int i = tid; i < 4096; i += 512) {
        int o = i >> 6, k = i & 63;
        float w = W1[o * 64 + k];
        __nv_bfloat16 h = __float2bfloat16(w);
        __nv_bfloat16 l = __float2bfloat16(w - __bfloat162float(h));
        uint32_t off = swz(o * 128 + 2 * k);
        *(__nv_bfloat16*)(smc + OW1H + off) = h;
        *(__nv_bfloat16*)(smc + OW1L + off) = l;
    }
    for (int i = tid; i < 8192; i += 512) {
        int o = i >> 6, k = i & 63;
        float w = W2[o * 64 + k];
        __nv_bfloat16 h = __float2bfloat16(w);
        __nv_bfloat16 l = __float2bfloat16(w - __bfloat162float(h));
        uint32_t off = swz(o * 128 + 2 * k);
        *(__nv_bfloat16*)(smc + OW2H + off) = h;
        *(__nv_bfloat16*)(smc + OW2L + off) = l;
    }
    for (int i = tid; i < 8192; i += 512) {
        int o = i >> 6, k = i & 63;
        float w = W3[o * 130 + 2 + k];
        __nv_bfloat16 h = __float2bfloat16(w);
        __nv_bfloat16 l = __float2bfloat16(w - __bfloat162float(h));
        uint32_t off = swz(o * 128 + 2 * k);
        *(__nv_bfloat16*)(smc + OW3AH + off) = h;
        *(__nv_bfloat16*)(smc + OW3AL + off) = l;
    }
    for (int i = tid; i < 8192; i += 512) {
        int o = i >> 6, k = i & 63;
        float w = W3[o * 130 + 66 + k];
        __nv_bfloat16 h = __float2bfloat16(w);
        __nv_bfloat16 l = __float2bfloat16(w - __bfloat162float(h));
        uint32_t off = swz(o * 128 + 2 * k);
        *(__nv_bfloat16*)(smc + OW3BH + off) = h;
        *(__nv_bfloat16*)(smc + OW3BL + off) = l;
    }
    if (tid < 128) {
        smf[OW0F / 4 + tid] = W0[tid];
        smf[OW3X / 4 + tid]       = W3[tid * 130];
        smf[OW3X / 4 + 128 + tid] = W3[tid * 130 + 1];
        if (tid < 64) { smf[OB0 / 4 + tid] = b0[tid]; smf[OB1 / 4 + tid] = b1[tid]; }
        smf[OB2 / 4 + tid] = b2[tid];
        smf[OB3 / 4 + tid] = b3[tid];
    }
    __syncthreads();

    // ---- group decomposition ----
    const int grp  = wid >> 3;               // 0 or 1
    const int tidg = tid & 255;              // thread within group
    const int wg   = wid & 7;
    const int mt   = wg >> 1;                // m-tile 0..3 (16 points each)
    const int nh   = wg & 1;                 // n-half
    const int gq   = lane >> 2;              // 0..7
    const int tq   = lane & 3;               // 0..3
    const int rp   = 16 * mt + gq;           // point row (and rp+8) within 64-pt tile

    const uint32_t gb   = sb + OGRP + grp * 49152;
    const uint32_t bAH = gb,          bAL = gb + 8192;
    const uint32_t bRH = gb + 16384,  bRL = gb + 24576;
    const uint32_t bCH = gb + 32768,  bCL = gb + 40960;
    float* xsf = smf + (OXS + grp * 512) / 4;     // [2][64]
    int*   ms  = (int*)(smc + OMS + grp * 256);   // [64]
    const int barid = grp + 1;

    #define GBAR() asm volatile("bar.sync %0, 256;" :: "r"(barid) : "memory")

    for (int t = blockIdx.x * 2 + grp; t < TILES64; t += 296) {
        int br = t / TPB64; int tloc = t - br * TPB64; int kn0 = tloc * 64;
        int b = br >> 2, r = br & 3;

        // ---- P0: xdec (fp32, exact) ----
        if (tidg < 64) {
            int kn = kn0 + tidg; int k = kn >> 12; int n = kn & (Nv - 1);
            float x0 = x[b * 2 * Nv + n], x1 = x[b * 2 * Nv + Nv + n];
            float cc, ss; rot_cs(r, cc, ss);
            float xr0 = cc * x0 - ss * x1;
            float xr1 = ss * x0 + cc * x1;
            int m = d_topk[(b * Nv + n) * 3 + k];
            xsf[tidg]      = xr0 - d_nrot[(br * 2 + 0) * Mv + m];
            xsf[64 + tidg] = xr1 - d_nrot[(br * 2 + 1) * Mv + m];
            ms[tidg] = m;
        }
        GBAR();

        // ---- L0 scalar (K=2): h1 -> tile A ----
        {
            int pp = tidg & 63, q = tidg >> 6;     // outs 16q..16q+15
            float x0 = xsf[pp], x1 = xsf[64 + pp];
            float v[16];
            #pragma unroll
            for (int j = 0; j < 16; j++) {
                int o = 16 * q + j;
                v[j] = fmaxf(fmaf(smf[OW0F / 4 + 2 * o], x0,
                             fmaf(smf[OW0F / 4 + 2 * o + 1], x1, smf[OB0 / 4 + o])), 0.f);
            }
            uint32_t ro = pp * 128 + 32 * q;
            pack_store8(bAH + swz(ro),      bAL + swz(ro),      v);
            pack_store8(bAH + swz(ro + 16), bAL + swz(ro + 16), v + 8);
        }
        GBAR();

        // ---- L1: h2 = relu(h1 x W1 + b1), N=64 ----
        {
            float acc[4][4];
            #pragma unroll
            for (int i = 0; i < 4; i++)
                #pragma unroll
                for (int j = 0; j < 4; j++) acc[i][j] = 0.f;
            int n0 = nh * 32;
            mma3<4>(acc, bAH, bAL, sb + OW1H, sb + OW1L, mt, n0, lane);
            #pragma unroll
            for (int nt = 0; nt < 4; nt++) {
                int o = n0 + 8 * nt + 2 * tq;
                float bv0 = smf[OB1 / 4 + o], bv1 = smf[OB1 / 4 + o + 1];
                st_pair(bRH, bRL, rp, o,
                        fmaxf(acc[nt][0] + bv0, 0.f), fmaxf(acc[nt][1] + bv1, 0.f));
                st_pair(bRH, bRL, rp + 8, o,
                        fmaxf(acc[nt][2] + bv0, 0.f), fmaxf(acc[nt][3] + bv1, 0.f));
            }
        }
        GBAR();

        // ---- L2: h3 = relu(h2 x W2 + b2), N=128 -> tiles A (o<64) / CB ----
        {
            float acc[8][4];
            #pragma unroll
            for (int i = 0; i < 8; i++)
                #pragma unroll
                for (int j = 0; j < 4; j++) acc[i][j] = 0.f;
            int n0 = nh * 64;
            mma3<8>(acc, bRH, bRL, sb + OW2H, sb + OW2L, mt, n0, lane);
            uint32_t hB = nh ? bCH : bAH;
            uint32_t lB = nh ? bCL : bAL;
            #pragma unroll
            for (int nt = 0; nt < 8; nt++) {
                int o = n0 + 8 * nt + 2 * tq;
                float bv0 = smf[OB2 / 4 + o], bv1 = smf[OB2 / 4 + o + 1];
                int oc = o & 63;
                st_pair(hB, lB, rp, oc,
                        fmaxf(acc[nt][0] + bv0, 0.f), fmaxf(acc[nt][1] + bv1, 0.f));
                st_pair(hB, lB, rp + 8, oc,
                        fmaxf(acc[nt][2] + bv0, 0.f), fmaxf(acc[nt][3] + bv1, 0.f));
            }
        }
        GBAR();

        // ---- L3: feat = relu(concat(x,h3) x W3 + b3), N=128 -> scatter-max ----
        {
            float acc[8][4];
            #pragma unroll
            for (int i = 0; i < 8; i++)
                #pragma unroll
                for (int j = 0; j < 4; j++) acc[i][j] = 0.f;
            int n0 = nh * 64;
            mma3<8>(acc, bAH, bAL, sb + OW3AH, sb + OW3AL, mt, n0, lane);
            mma3<8>(acc, bCH, bCL, sb + OW3BH, sb + OW3BL, mt, n0, lane);

            float x0a = xsf[rp],     x1a = xsf[64 + rp];
            float x0b = xsf[rp + 8], x1b = xsf[64 + rp + 8];
            int ma = ms[rp], mb = ms[rp + 8];
            unsigned* gpa = (unsigned*)&d_g[2 * P2 + br * Mv + ma];
            unsigned* gpb = (unsigned*)&d_g[2 * P2 + br * Mv + mb];
            bool put0 = (tloc == 0 && rp == 0);
            #pragma unroll
            for (int nt = 0; nt < 8; nt++) {
                int o = n0 + 8 * nt + 2 * tq;
                float w00 = smf[OW3X / 4 + o],       w10 = smf[OW3X / 4 + 128 + o];
                float w01 = smf[OW3X / 4 + o + 1],   w11 = smf[OW3X / 4 + 128 + o + 1];
                float bv0 = smf[OB3 / 4 + o],        bv1 = smf[OB3 / 4 + o + 1];
                float v0 = fmaxf(acc[nt][0] + bv0 + w00 * x0a + w10 * x1a, 0.f);
                float v1 = fmaxf(acc[nt][1] + bv1 + w01 * x0a + w11 * x1a, 0.f);
                float v2 = fmaxf(acc[nt][2] + bv0 + w00 * x0b + w10 * x1b, 0.f);
                float v3 = fmaxf(acc[nt][3] + bv1 + w01 * x0b + w11 * x1b, 0.f);
                atomicMax(gpa + o * P2,       __float_as_uint(v0));
                atomicMax(gpa + (o + 1) * P2, __float_as_uint(v1));
                atomicMax(gpb + o * P2,       __float_as_uint(v2));
                atomicMax(gpb + (o + 1) * P2, __float_as_uint(v3));
                if (put0) { d_fcol0[br * 128 + o] = v0; d_fcol0[br * 128 + o + 1] = v1; }
            }
        }
        GBAR();
    }
    #undef GBAR
}

// ---------------- K5: empty-cluster fallback ----------------
__global__ void k_fix() {
    int idx = blockIdx.x * 256 + threadIdx.x;
    int m = idx & 63; int c = (idx >> 6) & 127; int br = idx >> 13;
    int b = br >> 2;
    if (d_ccnt[b * Mv + m] == 0.f)
        d_g[(2 + c) * P2 + br * Mv + m] = d_fcol0[br * 128 + c];
}

// ---------------- gp GEMM + bias + ReLU (warp-uniform FFMA2) --------------
__global__ void __launch_bounds__(256) k_gemm(
    const float* __restrict__ W, const float* __restrict__ bias,
    const float* __restrict__ in1, int C1,
    const float* __restrict__ in2, int C2,
    float* __restrict__ out, int P)
{
    __shared__ __align__(16) float Wsh[16][68];
    __shared__ __align__(16) float Ish[16][68];
    const int C = C1 + C2;
    const int col0 = blockIdx.x * 64, ob0 = blockIdx.y * 64;
    const int tid = threadIdx.x;
    const int og = tid >> 5;
    const int cg = tid & 31;
    const int o0 = og * 8, p0 = cg * 2;
    unsigned long long acc[8];
    #pragma unroll
    for (int i = 0; i < 8; i++) acc[i] = 0ull;

    for (int k0 = 0; k0 < C; k0 += 16) {
        #pragma unroll
        for (int q = 0; q < 4; q++) {
            int l = tid * 4 + q; int oo = l >> 4, kk = l & 15;
            int c = k0 + kk;
            Wsh[kk][oo] = (c < C) ? W[(ob0 + oo) * C + c] : 0.f;
        }
        #pragma unroll
        for (int q = 0; q < 4; q++) {
            int l = tid * 4 + q; int kk = l >> 6, cc = l & 63;
            int c = k0 + kk;
            float v = 0.f;
            if (c < C1)      v = in1[c * P + col0 + cc];
            else if (c < C)  v = in2[(c - C1) * P + col0 + cc];
            Ish[kk][cc] = v;
        }
        __syncthreads();
        #pragma unroll
        for (int kk = 0; kk < 16; kk++) {
            float4 wA = *(const float4*)&Wsh[kk][o0];
            float4 wB = *(const float4*)&Wsh[kk][o0 + 4];
            unsigned long long a = *(const unsigned long long*)&Ish[kk][p0];
            acc[0] = ffma2(pack2(wA.x, wA.x), a, acc[0]);
            acc[1] = ffma2(pack2(wA.y, wA.y), a, acc[1]);
            acc[2] = ffma2(pack2(wA.z, wA.z), a, acc[2]);
            acc[3] = ffma2(pack2(wA.w, wA.w), a, acc[3]);
            acc[4] = ffma2(pack2(wB.x, wB.x), a, acc[4]);
            acc[5] = ffma2(pack2(wB.y, wB.y), a, acc[5]);
            acc[6] = ffma2(pack2(wB.z, wB.z), a, acc[6]);
            acc[7] = ffma2(pack2(wB.w, wB.w), a, acc[7]);
        }
        __syncthreads();
    }
    #pragma unroll
    for (int i = 0; i < 8; i++) {
        int o = ob0 + o0 + i;
        float bv = bias[o];
        float vl = fmaxf(lo2(acc[i]) + bv, 0.f);
        float vh = fmaxf(hi2(acc[i]) + bv, 0.f);
        *(float2*)&out[o * P + col0 + p0] = make_float2(vl, vh);
    }
}

// ---------------- K6: final max over (r, m) ----------------
__global__ void k_reduce(float* __restrict__ out) {
    int idx = blockIdx.x * 256 + threadIdx.x;
    int b = idx >> 9, f = idx & 511;
    const float* src = &d_D2[f * P2 + b * 256];
    float v = 0.f;
    #pragma unroll 8
    for (int j = 0; j < 256; j++) v = fmaxf(v, src[j]);
    out[b * Fv + f] = v;
}

// ---------------- host launcher ----------------
extern "C" void kernel_launch(void* const* d_in, const int* in_sizes, int n_in,
                              void* d_out, int out_size) {
    const float* x    = (const float*)d_in[0];
    const float* node = (const float*)d_in[2];
    const float* fpW0 = (const float*)d_in[4];  const float* fpb0 = (const float*)d_in[5];
    const float* fpW1 = (const float*)d_in[6];  const float* fpb1 = (const float*)d_in[7];
    const float* fpW2 = (const float*)d_in[8];  const float* fpb2 = (const float*)d_in[9];
    const float* fpW3 = (const float*)d_in[10]; const float* fpb3 = (const float*)d_in[11];
    const float* gpW0 = (const float*)d_in[12]; const float* gpb0 = (const float*)d_in[13];
    const float* gpW1 = (const float*)d_in[14]; const float* gpb1 = (const float*)d_in[15];
    const float* gpW2 = (const float*)d_in[16]; const float* gpb2 = (const float*)d_in[17];
    const float* gpW3 = (const float*)d_in[18]; const float* gpb3 = (const float*)d_in[19];

    float *p_g, *p_A, *p_B2, *p_C2, *p_D2;
    cudaGetSymbolAddress((void**)&p_g,  d_g);
    cudaGetSymbolAddress((void**)&p_A,  d_A);
    cudaGetSymbolAddress((void**)&p_B2, d_B2);
    cudaGetSymbolAddress((void**)&p_C2, d_C2);
    cudaGetSymbolAddress((void**)&p_D2, d_D2);

    cudaFuncSetAttribute(k_fp_mma, cudaFuncAttributeMaxDynamicSharedMemorySize, SMEM_TC);

    k_init<<<(130 * P2 + 255) / 256, 256>>>();
    k_topk<<<(Bv * Nv) / 256, 256>>>(x, node);
    k_nodes<<<1, 256>>>();

    k_fp_mma<<<148, 512, SMEM_TC>>>(x, fpW0, fpb0, fpW1, fpb1,
                                    fpW2, fpb2, fpW3, fpb3);
    k_fix<<<(BRv * 128 * Mv) / 256, 256>>>();

    k_gemm<<<dim3(P2 / 64, 4), 256>>>(gpW0, gpb0, p_g,  130, nullptr, 0,   p_A,  P2);
    k_gemm<<<dim3(P2 / 64, 4), 256>>>(gpW1, gpb1, p_A,  256, nullptr, 0,   p_B2, P2);
    k_gemm<<<dim3(P2 / 64, 8), 256>>>(gpW2, gpb2, p_B2, 256, nullptr, 0,   p_C2, P2);
    k_gemm<<<dim3(P2 / 64, 8), 256>>>(gpW3, gpb3, p_g,  130, p_C2,  512,   p_D2, P2);

    k_reduce<<<(Bv * Fv) / 256, 256>>>((float*)d_out);
}

// round 12
// speedup vs baseline: 1.2641x; 1.0257x over previous
#include <cuda_runtime.h>
#include <cuda_bf16.h>
#include <math.h>
#include <stdint.h>

// ---------------- problem constants ----------------
#define Bv   4
#define Rv   4
#define Nv   4096
#define Mv   64
#define KNv  12288
#define BRv  16
#define P1   196608
#define P2   1024
#define Fv   512
#define TILES64 3072         // P1 / 64
#define TPB64   192          // KN / 64

// ---------------- device scratch ----------------
__device__ int   d_topk[Bv * Nv * 3];
__device__ float d_csum[Bv * 2 * Mv];
__device__ float d_ccnt[Bv * Mv];
__device__ float d_nrot[BRv * 2 * Mv];
__device__ float d_g[130 * P2];
__device__ float d_fcol0[BRv * 128];
__device__ float d_A[256 * P2];
__device__ float d_B2[256 * P2];
__device__ float d_C2[512 * P2];
__device__ float d_D2[512 * P2];

// ---------------- scalar helpers ----------------
__device__ __forceinline__ unsigned long long ffma2(unsigned long long a,
                                                    unsigned long long b,
                                                    unsigned long long c) {
    unsigned long long d;
    asm("fma.rn.f32x2 %0, %1, %2, %3;" : "=l"(d) : "l"(a), "l"(b), "l"(c));
    return d;
}
__device__ __forceinline__ unsigned long long pack2(float lo, float hi) {
    unsigned long long r;
    asm("mov.b64 %0, {%1, %2};" : "=l"(r) : "f"(lo), "f"(hi));
    return r;
}
__device__ __forceinline__ float lo2(unsigned long long a) { return __uint_as_float((unsigned)a); }
__device__ __forceinline__ float hi2(unsigned long long a) { return __uint_as_float((unsigned)(a >> 32)); }

__device__ __forceinline__ void rot_cs(int r, float& c, float& s) {
    float th = 6.2831855f * (float)r * 0.25f;
    c = cosf(th);
    s = sinf(th);
}
__device__ __forceinline__ uint32_t smem_u32(const void* p) {
    uint32_t a;
    asm("{ .reg .u64 t; cvta.to.shared.u64 t, %1; cvt.u32.u64 %0, t; }" : "=r"(a) : "l"(p));
    return a;
}
__device__ __forceinline__ uint32_t swz(uint32_t b) { return b ^ ((b >> 3) & 0x70); }

// ---------------- warp MMA helpers ----------------
__device__ __forceinline__ void ldsm4(uint32_t* r, uint32_t addr) {
    asm volatile("ldmatrix.sync.aligned.m8n8.x4.shared.b16 {%0,%1,%2,%3}, [%4];"
                 : "=r"(r[0]), "=r"(r[1]), "=r"(r[2]), "=r"(r[3]) : "r"(addr));
}
__device__ __forceinline__ void mma16816(float* d, const uint32_t* a, const uint32_t* b) {
    asm volatile("mma.sync.aligned.m16n8k16.row.col.f32.bf16.bf16.f32 "
                 "{%0,%1,%2,%3}, {%4,%5,%6,%7}, {%8,%9}, {%0,%1,%2,%3};"
                 : "+f"(d[0]), "+f"(d[1]), "+f"(d[2]), "+f"(d[3])
                 : "r"(a[0]), "r"(a[1]), "r"(a[2]), "r"(a[3]), "r"(b[0]), "r"(b[1]));
}

// m-paired hi/lo 3-combo pass: warp covers m-tiles {mt0, mt0+1} x NT n-tiles.
// Weight fragments register-shared across both m-tiles; combo-grouped for ILP.
// acc layout: acc[mt * NT + nt][4]
template<int NT>
__device__ __forceinline__ void mma3p(float acc[][4], uint32_t aHb, uint32_t aLb,
                                      uint32_t wHb, uint32_t wLb, int mt0, int n0, int lane) {
    const int abase = (lane & 7) + ((lane >> 3) & 1) * 8;
    const int aoff = ((lane >> 4) & 1) * 16;
    const int arow0 = 16 * mt0 + abase;
    const int arow1 = arow0 + 16;
    const int brow = (lane & 7) + (lane >> 4) * 8;
    const int boff = ((lane >> 3) & 1) * 16;
    #pragma unroll
    for (int ks = 0; ks < 4; ks++) {
        uint32_t aH0[4], aL0[4], aH1[4], aL1[4];
        uint32_t a0s = swz((uint32_t)(arow0 * 128 + 32 * ks + aoff));
        uint32_t a1s = swz((uint32_t)(arow1 * 128 + 32 * ks + aoff));
        ldsm4(aH0, aHb + a0s);
        ldsm4(aH1, aHb + a1s);
        ldsm4(aL0, aLb + a0s);
        ldsm4(aL1, aLb + a1s);
        uint32_t roffs[NT / 2];
        uint32_t wf[NT / 2][4];
        #pragma unroll
        for (int u = 0; u < NT / 2; u++) {
            roffs[u] = swz((uint32_t)((n0 + 16 * u + brow) * 128 + 32 * ks + boff));
            ldsm4(wf[u], wHb + roffs[u]);
        }
        #pragma unroll
        for (int u = 0; u < NT / 2; u++) {       // Ah x Wh, both m-tiles
            mma16816(acc[2 * u],          aH0, wf[u]); mma16816(acc[2 * u + 1],      aH0, wf[u] + 2);
            mma16816(acc[NT + 2 * u],     aH1, wf[u]); mma16816(acc[NT + 2 * u + 1], aH1, wf[u] + 2);
        }
        #pragma unroll
        for (int u = 0; u < NT / 2; u++) {       // Al x Wh
            mma16816(acc[2 * u],          aL0, wf[u]); mma16816(acc[2 * u + 1],      aL0, wf[u] + 2);
            mma16816(acc[NT + 2 * u],     aL1, wf[u]); mma16816(acc[NT + 2 * u + 1], aL1, wf[u] + 2);
        }
        #pragma unroll
        for (int u = 0; u < NT / 2; u++)
            ldsm4(wf[u], wLb + roffs[u]);
        #pragma unroll
        for (int u = 0; u < NT / 2; u++) {       // Ah x Wl
            mma16816(acc[2 * u],          aH0, wf[u]); mma16816(acc[2 * u + 1],      aH0, wf[u] + 2);
            mma16816(acc[NT + 2 * u],     aH1, wf[u]); mma16816(acc[NT + 2 * u + 1], aH1, wf[u] + 2);
        }
    }
}

// store bf16 hi/lo pair (cols o, o+1) at point row p
__device__ __forceinline__ void st_pair(uint32_t hB, uint32_t lB, int p, int o,
                                        float v0, float v1) {
    uint32_t h, l;
    asm("cvt.rn.bf16x2.f32 %0, %1, %2;" : "=r"(h) : "f"(v1), "f"(v0));
    float h0 = __uint_as_float(h << 16);
    float h1 = __uint_as_float(h & 0xffff0000u);
    asm("cvt.rn.bf16x2.f32 %0, %1, %2;" : "=r"(l) : "f"(v1 - h1), "f"(v0 - h0));
    uint32_t off = swz((uint32_t)(p * 128 + 2 * o));
    asm volatile("st.shared.b32 [%0], %1;" :: "r"(hB + off), "r"(h) : "memory");
    asm volatile("st.shared.b32 [%0], %1;" :: "r"(lB + off), "r"(l) : "memory");
}

// pack 8 fp32 -> 16B bf16-hi + 16B bf16-lo (for L0)
__device__ __forceinline__ void pack_store8(uint32_t addrH, uint32_t addrL, const float* v) {
    uint32_t h[4], l[4];
    #pragma unroll
    for (int q = 0; q < 4; q++) {
        float a = v[2 * q], b = v[2 * q + 1];
        asm("cvt.rn.bf16x2.f32 %0, %1, %2;" : "=r"(h[q]) : "f"(b), "f"(a));
        float ha = __uint_as_float(h[q] << 16);
        float hb = __uint_as_float(h[q] & 0xffff0000u);
        asm("cvt.rn.bf16x2.f32 %0, %1, %2;" : "=r"(l[q]) : "f"(b - hb), "f"(a - ha));
    }
    asm volatile("st.shared.v4.b32 [%0], {%1, %2, %3, %4};"
                 :: "r"(addrH), "r"(h[0]), "r"(h[1]), "r"(h[2]), "r"(h[3]) : "memory");
    asm volatile("st.shared.v4.b32 [%0], {%1, %2, %3, %4};"
                 :: "r"(addrL), "r"(l[0]), "r"(l[1]), "r"(l[2]), "r"(l[3]) : "memory");
}

// ---------------- K0 ----------------
__global__ void k_init() {
    int i = blockIdx.x * 256 + threadIdx.x;
    if (i < Bv * 2 * Mv) d_csum[i] = 0.f;
    if (i < Bv * Mv)     d_ccnt[i] = 0.f;
    if (i < 130 * P2)    d_g[i]    = 0.f;
}

// ---------------- K1: top-3 + cluster accumulation ----------
__global__ void k_topk(const float* __restrict__ x, const float* __restrict__ node) {
    int idx = blockIdx.x * 256 + threadIdx.x;
    if (idx >= Bv * Nv) return;
    int b = idx >> 12, n = idx & (Nv - 1);
    float x0 = x[b * 2 * Nv + n];
    float x1 = x[b * 2 * Nv + Nv + n];
    float d0 = 3.4e38f, d1 = 3.4e38f, d2 = 3.4e38f;
    int   i0 = 0, i1 = 0, i2 = 0;
    #pragma unroll
    for (int m = 0; m < Mv; m++) {
        float dx = x0 - __ldg(&node[b * 2 * Mv + m]);
        float dy = x1 - __ldg(&node[b * 2 * Mv + Mv + m]);
        float d = dx * dx + dy * dy;
        if (d < d0)      { d2 = d1; i2 = i1; d1 = d0; i1 = i0; d0 = d; i0 = m; }
        else if (d < d1) { d2 = d1; i2 = i1; d1 = d;  i1 = m; }
        else if (d < d2) { d2 = d;  i2 = m; }
    }
    int o = idx * 3;
    d_topk[o] = i0; d_topk[o + 1] = i1; d_topk[o + 2] = i2;
    atomicAdd(&d_csum[b * 2 * Mv + i0],      x0);
    atomicAdd(&d_csum[b * 2 * Mv + Mv + i0], x1);
    atomicAdd(&d_ccnt[b * Mv + i0], 1.f);
    atomicAdd(&d_csum[b * 2 * Mv + i1],      x0);
    atomicAdd(&d_csum[b * 2 * Mv + Mv + i1], x1);
    atomicAdd(&d_ccnt[b * Mv + i1], 1.f);
    atomicAdd(&d_csum[b * 2 * Mv + i2],      x0);
    atomicAdd(&d_csum[b * 2 * Mv + Mv + i2], x1);
    atomicAdd(&d_ccnt[b * Mv + i2], 1.f);
}

// ---------------- K2 ----------------
__global__ void k_nodes() {
    int idx = threadIdx.x;
    int b = idx >> 6, m = idx & 63;
    float cnt = d_ccnt[b * Mv + m];
    float inv = 1.f / (cnt + 1e-5f);
    float m0 = d_csum[b * 2 * Mv + m]      * inv;
    float m1 = d_csum[b * 2 * Mv + Mv + m] * inv;
    #pragma unroll
    for (int r = 0; r < Rv; r++) {
        float c, s; rot_cs(r, c, s);
        float n0 = c * m0 - s * m1;
        float n1 = s * m0 + c * m1;
        int br = b * Rv + r;
        d_nrot[(br * 2 + 0) * Mv + m] = n0;
        d_nrot[(br * 2 + 1) * Mv + m] = n1;
        d_g[0 * P2 + br * Mv + m] = n0;
        d_g[1 * P2 + br * Mv + m] = n1;
    }
}

// ---------------- warp-MMA fused fp block (2 groups, m-paired warps) -------
// smem byte offsets
#define OW1H  0         // W1 hi  [64o][64k]
#define OW1L  8192
#define OW2H  16384     // W2 hi  [128o][64k]
#define OW2L  32768
#define OW3AH 49152     // W3 k=2..65
#define OW3AL 65536
#define OW3BH 81920     // W3 k=66..129
#define OW3BL 98304
#define OGRP  114688    // group act buffers: 2 x 48KB
#define OW0F  212992    // W0 fp32 [128]
#define OW3X  213504    // W3 x-part fp32 [256]
#define OB0   214528
#define OB1   214784
#define OB2   215040
#define OB3   215552
#define OXS   216064    // per-group xdec fp32 [128]
#define OMS   217088    // per-group int [64]
#define SMEM_TC 217600

__global__ void __launch_bounds__(512, 1) k_fp_mma(
    const float* __restrict__ x,
    const float* __restrict__ W0, const float* __restrict__ b0,
    const float* __restrict__ W1, const float* __restrict__ b1,
    const float* __restrict__ W2, const float* __restrict__ b2,
    const float* __restrict__ W3, const float* __restrict__ b3)
{
    extern __shared__ __align__(1024) char smc[];
    float* smf = (float*)smc;
    const int tid  = threadIdx.x;
    const int wid  = tid >> 5;
    const int lane = tid & 31;
    const uint32_t sb = smem_u32(smc);

    // ---- one-time: weights -> bf16 hi/lo swizzled K-major tiles ----
    for (int i = tid; i < 4096; i += 512) {
        int o = i >> 6, k = i & 63;
        float w = W1[o * 64 + k];
        __nv_bfloat16 h = __float2bfloat16(w);
        __nv_bfloat16 l = __float2bfloat16(w - __bfloat162float(h));
        uint32_t off = swz(o * 128 + 2 * k);
        *(__nv_bfloat16*)(smc + OW1H + off) = h;
        *(__nv_bfloat16*)(smc + OW1L + off) = l;
    }
    for (int i = tid; i < 8192; i += 512) {
        int o = i >> 6, k = i & 63;
        float w = W2[o * 64 + k];
        __nv_bfloat16 h = __float2bfloat16(w);
        __nv_bfloat16 l = __float2bfloat16(w - __bfloat162float(h));
        uint32_t off = swz(o * 128 + 2 * k);
        *(__nv_bfloat16*)(smc + OW2H + off) = h;
        *(__nv_bfloat16*)(smc + OW2L + off) = l;
    }
    for (int i = tid; i < 8192; i += 512) {
        int o = i >> 6, k = i & 63;
        float w = W3[o * 130 + 2 + k];
        __nv_bfloat16 h = __float2bfloat16(w);
        __nv_bfloat16 l = __float2bfloat16(w - __bfloat162float(h));
        uint32_t off = swz(o * 128 + 2 * k);
        *(__nv_bfloat16*)(smc + OW3AH + off) = h;
        *(__nv_bfloat16*)(smc + OW3AL + off) = l;
    }
    for (int i = tid; i < 8192; i += 512) {
        int o = i >> 6, k = i & 63;
        float w = W3[o * 130 + 66 + k];
        __nv_bfloat16 h = __float2bfloat16(w);
        __nv_bfloat16 l = __float2bfloat16(w - __bfloat162float(h));
        uint32_t off = swz(o * 128 + 2 * k);
        *(__nv_bfloat16*)(smc + OW3BH + off) = h;
        *(__nv_bfloat16*)(smc + OW3BL + off) = l;
    }
    if (tid < 128) {
        smf[OW0F / 4 + tid] = W0[tid];
        smf[OW3X / 4 + tid]       = W3[tid * 130];
        smf[OW3X / 4 + 128 + tid] = W3[tid * 130 + 1];
        if (tid < 64) { smf[OB0 / 4 + tid] = b0[tid]; smf[OB1 / 4 + tid] = b1[tid]; }
        smf[OB2 / 4 + tid] = b2[tid];
        smf[OB3 / 4 + tid] = b3[tid];
    }
    __syncthreads();

    // ---- group decomposition: 2 groups x 8 warps; warp = 2 m-tiles x 1 n-quarter
    const int grp  = wid >> 3;               // 0 or 1
    const int tidg = tid & 255;
    const int wg   = wid & 7;
    const int mp   = wg >> 2;                // m-pair 0..1
    const int nq   = wg & 3;                 // n-quarter 0..3
    const int mt0  = 2 * mp;                 // first m-tile of pair
    const int gq   = lane >> 2;              // 0..7
    const int tq   = lane & 3;               // 0..3

    const uint32_t gb  = sb + OGRP + grp * 49152;
    const uint32_t bAH = gb,          bAL = gb + 8192;
    const uint32_t bRH = gb + 16384,  bRL = gb + 24576;
    const uint32_t bCH = gb + 32768,  bCL = gb + 40960;
    float* xsf = smf + (OXS + grp * 512) / 4;     // [2][64]
    int*   ms  = (int*)(smc + OMS + grp * 256);   // [64]
    const int barid = grp + 1;

    #define GBAR() asm volatile("bar.sync %0, 256;" :: "r"(barid) : "memory")

    for (int t = blockIdx.x * 2 + grp; t < TILES64; t += 296) {
        int br = t / TPB64; int tloc = t - br * TPB64; int kn0 = tloc * 64;
        int b = br >> 2, r = br & 3;

        // ---- P0: xdec (fp32, exact) ----
        if (tidg < 64) {
            int kn = kn0 + tidg; int k = kn >> 12; int n = kn & (Nv - 1);
            float x0 = x[b * 2 * Nv + n], x1 = x[b * 2 * Nv + Nv + n];
            float cc, ss; rot_cs(r, cc, ss);
            float xr0 = cc * x0 - ss * x1;
            float xr1 = ss * x0 + cc * x1;
            int m = d_topk[(b * Nv + n) * 3 + k];
            xsf[tidg]      = xr0 - d_nrot[(br * 2 + 0) * Mv + m];
            xsf[64 + tidg] = xr1 - d_nrot[(br * 2 + 1) * Mv + m];
            ms[tidg] = m;
        }
        GBAR();

        // ---- L0 scalar (K=2): h1 -> tile A ----
        {
            int pp = tidg & 63, q = tidg >> 6;
            float x0 = xsf[pp], x1 = xsf[64 + pp];
            float v[16];
            #pragma unroll
            for (int j = 0; j < 16; j++) {
                int o = 16 * q + j;
                v[j] = fmaxf(fmaf(smf[OW0F / 4 + 2 * o], x0,
                             fmaf(smf[OW0F / 4 + 2 * o + 1], x1, smf[OB0 / 4 + o])), 0.f);
            }
            uint32_t ro = pp * 128 + 32 * q;
            pack_store8(bAH + swz(ro),      bAL + swz(ro),      v);
            pack_store8(bAH + swz(ro + 16), bAL + swz(ro + 16), v + 8);
        }
        GBAR();

        // ---- L1: h2 = relu(h1 x W1 + b1), N=64, warp: 2mt x 16 outs ----
        {
            float acc[4][4];
            #pragma unroll
            for (int i = 0; i < 4; i++)
                #pragma unroll
                for (int j = 0; j < 4; j++) acc[i][j] = 0.f;
            int n0 = nq * 16;
            mma3p<2>(acc, bAH, bAL, sb + OW1H, sb + OW1L, mt0, n0, lane);
            #pragma unroll
            for (int mt = 0; mt < 2; mt++) {
                int rp = 16 * (mt0 + mt) + gq;
                #pragma unroll
                for (int nt = 0; nt < 2; nt++) {
                    int o = n0 + 8 * nt + 2 * tq;
                    float bv0 = smf[OB1 / 4 + o], bv1 = smf[OB1 / 4 + o + 1];
                    float* a = acc[mt * 2 + nt];
                    st_pair(bRH, bRL, rp, o,
                            fmaxf(a[0] + bv0, 0.f), fmaxf(a[1] + bv1, 0.f));
                    st_pair(bRH, bRL, rp + 8, o,
                            fmaxf(a[2] + bv0, 0.f), fmaxf(a[3] + bv1, 0.f));
                }
            }
        }
        GBAR();

        // ---- L2: h3 = relu(h2 x W2 + b2), N=128, warp: 2mt x 32 outs ----
        {
            float acc[8][4];
            #pragma unroll
            for (int i = 0; i < 8; i++)
                #pragma unroll
                for (int j = 0; j < 4; j++) acc[i][j] = 0.f;
            int n0 = nq * 32;
            mma3p<4>(acc, bRH, bRL, sb + OW2H, sb + OW2L, mt0, n0, lane);
            uint32_t hB = (nq < 2) ? bAH : bCH;
            uint32_t lB = (nq < 2) ? bAL : bCL;
            #pragma unroll
            for (int mt = 0; mt < 2; mt++) {
                int rp = 16 * (mt0 + mt) + gq;
                #pragma unroll
                for (int nt = 0; nt < 4; nt++) {
                    int o = n0 + 8 * nt + 2 * tq;
                    float bv0 = smf[OB2 / 4 + o], bv1 = smf[OB2 / 4 + o + 1];
                    int oc = o & 63;
                    float* a = acc[mt * 4 + nt];
                    st_pair(hB, lB, rp, oc,
                            fmaxf(a[0] + bv0, 0.f), fmaxf(a[1] + bv1, 0.f));
                    st_pair(hB, lB, rp + 8, oc,
                            fmaxf(a[2] + bv0, 0.f), fmaxf(a[3] + bv1, 0.f));
                }
            }
        }
        GBAR();

        // ---- L3: feat = relu(concat(x,h3) x W3 + b3), N=128 -> scatter-max ----
        {
            float acc[8][4];
            #pragma unroll
            for (int i = 0; i < 8; i++)
                #pragma unroll
                for (int j = 0; j < 4; j++) acc[i][j] = 0.f;
            int n0 = nq * 32;
            mma3p<4>(acc, bAH, bAL, sb + OW3AH, sb + OW3AL, mt0, n0, lane);
            mma3p<4>(acc, bCH, bCL, sb + OW3BH, sb + OW3BL, mt0, n0, lane);

            #pragma unroll
            for (int mt = 0; mt < 2; mt++) {
                int rp = 16 * (mt0 + mt) + gq;
                float x0a = xsf[rp],     x1a = xsf[64 + rp];
                float x0b = xsf[rp + 8], x1b = xsf[64 + rp + 8];
                int ma = ms[rp], mb = ms[rp + 8];
                unsigned* gpa = (unsigned*)&d_g[2 * P2 + br * Mv + ma];
                unsigned* gpb = (unsigned*)&d_g[2 * P2 + br * Mv + mb];
                bool put0 = (tloc == 0 && rp == 0);
                #pragma unroll
                for (int nt = 0; nt < 4; nt++) {
                    int o = n0 + 8 * nt + 2 * tq;
                    float w00 = smf[OW3X / 4 + o],     w10 = smf[OW3X / 4 + 128 + o];
                    float w01 = smf[OW3X / 4 + o + 1], w11 = smf[OW3X / 4 + 128 + o + 1];
                    float bv0 = smf[OB3 / 4 + o],      bv1 = smf[OB3 / 4 + o + 1];
                    float* a = acc[mt * 4 + nt];
                    float v0 = fmaxf(a[0] + bv0 + w00 * x0a + w10 * x1a, 0.f);
                    float v1 = fmaxf(a[1] + bv1 + w01 * x0a + w11 * x1a, 0.f);
                    float v2 = fmaxf(a[2] + bv0 + w00 * x0b + w10 * x1b, 0.f);
                    float v3 = fmaxf(a[3] + bv1 + w01 * x0b + w11 * x1b, 0.f);
                    atomicMax(gpa + o * P2,       __float_as_uint(v0));
                    atomicMax(gpa + (o + 1) * P2, __float_as_uint(v1));
                    atomicMax(gpb + o * P2,       __float_as_uint(v2));
                    atomicMax(gpb + (o + 1) * P2, __float_as_uint(v3));
                    if (put0) { d_fcol0[br * 128 + o] = v0; d_fcol0[br * 128 + o + 1] = v1; }
                }
            }
        }
        GBAR();
    }
    #undef GBAR
}

// ---------------- K5: empty-cluster fallback ----------------
__global__ void k_fix() {
    int idx = blockIdx.x * 256 + threadIdx.x;
    int m = idx & 63; int c = (idx >> 6) & 127; int br = idx >> 13;
    int b = br >> 2;
    if (d_ccnt[b * Mv + m] == 0.f)
        d_g[(2 + c) * P2 + br * Mv + m] = d_fcol0[br * 128 + c];
}

// ---------------- gp GEMM + bias + ReLU (32 outs x 64 cols, 128 thr) -------
__global__ void __launch_bounds__(128) k_gemm(
    const float* __restrict__ W, const float* __restrict__ bias,
    const float* __restrict__ in1, int C1,
    const float* __restrict__ in2, int C2,
    float* __restrict__ out, int P)
{
    __shared__ __align__(16) float Wsh[16][36];
    __shared__ __align__(16) float Ish[16][68];
    const int C = C1 + C2;
    const int col0 = blockIdx.x * 64, ob0 = blockIdx.y * 32;
    const int tid = threadIdx.x;
    const int og = tid >> 5;            // 0..3 (uniform per warp)
    const int cg = tid & 31;
    const int o0 = og * 8, p0 = cg * 2;
    unsigned long long acc[8];
    #pragma unroll
    for (int i = 0; i < 8; i++) acc[i] = 0ull;

    for (int k0 = 0; k0 < C; k0 += 16) {
        #pragma unroll
        for (int q = 0; q < 4; q++) {
            int l = tid * 4 + q; int oo = l >> 4, kk = l & 15;
            int c = k0 + kk;
            Wsh[kk][oo] = (c < C) ? W[(ob0 + oo) * C + c] : 0.f;
        }
        #pragma unroll
        for (int q = 0; q < 8; q++) {
            int l = tid * 8 + q; int kk = l >> 6, cc = l & 63;
            int c = k0 + kk;
            float v = 0.f;
            if (c < C1)      v = in1[c * P + col0 + cc];
            else if (c < C)  v = in2[(c - C1) * P + col0 + cc];
            Ish[kk][cc] = v;
        }
        __syncthreads();
        #pragma unroll
        for (int kk = 0; kk < 16; kk++) {
            float4 wA = *(const float4*)&Wsh[kk][o0];
            float4 wB = *(const float4*)&Wsh[kk][o0 + 4];
            unsigned long long a = *(const unsigned long long*)&Ish[kk][p0];
            acc[0] = ffma2(pack2(wA.x, wA.x), a, acc[0]);
            acc[1] = ffma2(pack2(wA.y, wA.y), a, acc[1]);
            acc[2] = ffma2(pack2(wA.z, wA.z), a, acc[2]);
            acc[3] = ffma2(pack2(wA.w, wA.w), a, acc[3]);
            acc[4] = ffma2(pack2(wB.x, wB.x), a, acc[4]);
            acc[5] = ffma2(pack2(wB.y, wB.y), a, acc[5]);
            acc[6] = ffma2(pack2(wB.z, wB.z), a, acc[6]);
            acc[7] = ffma2(pack2(wB.w, wB.w), a, acc[7]);
        }
        __syncthreads();
    }
    #pragma unroll
    for (int i = 0; i < 8; i++) {
        int o = ob0 + o0 + i;
        float bv = bias[o];
        float vl = fmaxf(lo2(acc[i]) + bv, 0.f);
        float vh = fmaxf(hi2(acc[i]) + bv, 0.f);
        *(float2*)&out[o * P + col0 + p0] = make_float2(vl, vh);
    }
}

// ---------------- K6: final max over (r, m) ----------------
__global__ void k_reduce(float* __restrict__ out) {
    int idx = blockIdx.x * 256 + threadIdx.x;
    int b = idx >> 9, f = idx & 511;
    const float* src = &d_D2[f * P2 + b * 256];
    float v = 0.f;
    #pragma unroll 8
    for (int j = 0; j < 256; j++) v = fmaxf(v, src[j]);
    out[b * Fv + f] = v;
}

// ---------------- host launcher ----------------
extern "C" void kernel_launch(void* const* d_in, const int* in_sizes, int n_in,
                              void* d_out, int out_size) {
    const float* x    = (const float*)d_in[0];
    const float* node = (const float*)d_in[2];
    const float* fpW0 = (const float*)d_in[4];  const float* fpb0 = (const float*)d_in[5];
    const float* fpW1 = (const float*)d_in[6];  const float* fpb1 = (const float*)d_in[7];
    const float* fpW2 = (const float*)d_in[8];  const float* fpb2 = (const float*)d_in[9];
    const float* fpW3 = (const float*)d_in[10]; const float* fpb3 = (const float*)d_in[11];
    const float* gpW0 = (const float*)d_in[12]; const float* gpb0 = (const float*)d_in[13];
    const float* gpW1 = (const float*)d_in[14]; const float* gpb1 = (const float*)d_in[15];
    const float* gpW2 = (const float*)d_in[16]; const float* gpb2 = (const float*)d_in[17];
    const float* gpW3 = (const float*)d_in[18]; const float* gpb3 = (const float*)d_in[19];

    float *p_g, *p_A, *p_B2, *p_C2, *p_D2;
    cudaGetSymbolAddress((void**)&p_g,  d_g);
    cudaGetSymbolAddress((void**)&p_A,  d_A);
    cudaGetSymbolAddress((void**)&p_B2, d_B2);
    cudaGetSymbolAddress((void**)&p_C2, d_C2);
    cudaGetSymbolAddress((void**)&p_D2, d_D2);

    cudaFuncSetAttribute(k_fp_mma, cudaFuncAttributeMaxDynamicSharedMemorySize, SMEM_TC);

    k_init<<<(130 * P2 + 255) / 256, 256>>>();
    k_topk<<<(Bv * Nv) / 256, 256>>>(x, node);
    k_nodes<<<1, 256>>>();

    k_fp_mma<<<148, 512, SMEM_TC>>>(x, fpW0, fpb0, fpW1, fpb1,
                                    fpW2, fpb2, fpW3, fpb3);
    k_fix<<<(BRv * 128 * Mv) / 256, 256>>>();

    k_gemm<<<dim3(P2 / 64, 8),  128>>>(gpW0, gpb0, p_g,  130, nullptr, 0,   p_A,  P2);
    k_gemm<<<dim3(P2 / 64, 8),  128>>>(gpW1, gpb1, p_A,  256, nullptr, 0,   p_B2, P2);
    k_gemm<<<dim3(P2 / 64, 16), 128>>>(gpW2, gpb2, p_B2, 256, nullptr, 0,   p_C2, P2);
    k_gemm<<<dim3(P2 / 64, 16), 128>>>(gpW3, gpb3, p_g,  130, p_C2,  512,   p_D2, P2);

    k_reduce<<<(Bv * Fv) / 256, 256>>>((float*)d_out);
}

// round 13
// speedup vs baseline: 1.3376x; 1.0581x over previous
#include <cuda_runtime.h>
#include <cuda_bf16.h>
#include <math.h>
#include <stdint.h>

// ---------------- problem constants ----------------
#define Bv   4
#define Rv   4
#define Nv   4096
#define Mv   64
#define KNv  12288
#define BRv  16
#define P1   196608
#define P2   1024
#define Fv   512
#define TILES64 3072         // P1 / 64
#define TPB64   192          // KN / 64

// ---------------- device scratch ----------------
__device__ int   d_topk[Bv * Nv * 3];
__device__ float d_csum[Bv * 2 * Mv];
__device__ float d_ccnt[Bv * Mv];
__device__ float d_nrot[BRv * 2 * Mv];
__device__ float d_g[130 * P2];
__device__ float d_fcol0[BRv * 128];
__device__ float d_A[256 * P2];
__device__ float d_B2[256 * P2];
__device__ float d_C2[512 * P2];
__device__ float d_D2[512 * P2];

// ---------------- scalar helpers ----------------
__device__ __forceinline__ unsigned long long ffma2(unsigned long long a,
                                                    unsigned long long b,
                                                    unsigned long long c) {
    unsigned long long d;
    asm("fma.rn.f32x2 %0, %1, %2, %3;" : "=l"(d) : "l"(a), "l"(b), "l"(c));
    return d;
}
__device__ __forceinline__ unsigned long long pack2(float lo, float hi) {
    unsigned long long r;
    asm("mov.b64 %0, {%1, %2};" : "=l"(r) : "f"(lo), "f"(hi));
    return r;
}
__device__ __forceinline__ float lo2(unsigned long long a) { return __uint_as_float((unsigned)a); }
__device__ __forceinline__ float hi2(unsigned long long a) { return __uint_as_float((unsigned)(a >> 32)); }

__device__ __forceinline__ void rot_cs(int r, float& c, float& s) {
    float th = 6.2831855f * (float)r * 0.25f;
    c = cosf(th);
    s = sinf(th);
}
__device__ __forceinline__ uint32_t smem_u32(const void* p) {
    uint32_t a;
    asm("{ .reg .u64 t; cvta.to.shared.u64 t, %1; cvt.u32.u64 %0, t; }" : "=r"(a) : "l"(p));
    return a;
}
__device__ __forceinline__ uint32_t swz(uint32_t b) { return b ^ ((b >> 3) & 0x70); }

// ---------------- warp MMA helpers ----------------
__device__ __forceinline__ void ldsm4(uint32_t* r, uint32_t addr) {
    asm volatile("ldmatrix.sync.aligned.m8n8.x4.shared.b16 {%0,%1,%2,%3}, [%4];"
                 : "=r"(r[0]), "=r"(r[1]), "=r"(r[2]), "=r"(r[3]) : "r"(addr));
}
__device__ __forceinline__ void mma16816(float* d, const uint32_t* a, const uint32_t* b) {
    asm volatile("mma.sync.aligned.m16n8k16.row.col.f32.bf16.bf16.f32 "
                 "{%0,%1,%2,%3}, {%4,%5,%6,%7}, {%8,%9}, {%0,%1,%2,%3};"
                 : "+f"(d[0]), "+f"(d[1]), "+f"(d[2]), "+f"(d[3])
                 : "r"(a[0]), "r"(a[1]), "r"(a[2]), "r"(a[3]), "r"(b[0]), "r"(b[1]));
}

// m-paired hi/lo 3-combo pass (as R12)
template<int NT>
__device__ __forceinline__ void mma3p(float acc[][4], uint32_t aHb, uint32_t aLb,
                                      uint32_t wHb, uint32_t wLb, int mt0, int n0, int lane) {
    const int abase = (lane & 7) + ((lane >> 3) & 1) * 8;
    const int aoff = ((lane >> 4) & 1) * 16;
    const int arow0 = 16 * mt0 + abase;
    const int arow1 = arow0 + 16;
    const int brow = (lane & 7) + (lane >> 4) * 8;
    const int boff = ((lane >> 3) & 1) * 16;
    #pragma unroll
    for (int ks = 0; ks < 4; ks++) {
        uint32_t aH0[4], aL0[4], aH1[4], aL1[4];
        uint32_t a0s = swz((uint32_t)(arow0 * 128 + 32 * ks + aoff));
        uint32_t a1s = swz((uint32_t)(arow1 * 128 + 32 * ks + aoff));
        ldsm4(aH0, aHb + a0s);
        ldsm4(aH1, aHb + a1s);
        ldsm4(aL0, aLb + a0s);
        ldsm4(aL1, aLb + a1s);
        uint32_t roffs[NT / 2];
        uint32_t wf[NT / 2][4];
        #pragma unroll
        for (int u = 0; u < NT / 2; u++) {
            roffs[u] = swz((uint32_t)((n0 + 16 * u + brow) * 128 + 32 * ks + boff));
            ldsm4(wf[u], wHb + roffs[u]);
        }
        #pragma unroll
        for (int u = 0; u < NT / 2; u++) {
            mma16816(acc[2 * u],          aH0, wf[u]); mma16816(acc[2 * u + 1],      aH0, wf[u] + 2);
            mma16816(acc[NT + 2 * u],     aH1, wf[u]); mma16816(acc[NT + 2 * u + 1], aH1, wf[u] + 2);
        }
        #pragma unroll
        for (int u = 0; u < NT / 2; u++) {
            mma16816(acc[2 * u],          aL0, wf[u]); mma16816(acc[2 * u + 1],      aL0, wf[u] + 2);
            mma16816(acc[NT + 2 * u],     aL1, wf[u]); mma16816(acc[NT + 2 * u + 1], aL1, wf[u] + 2);
        }
        #pragma unroll
        for (int u = 0; u < NT / 2; u++)
            ldsm4(wf[u], wLb + roffs[u]);
        #pragma unroll
        for (int u = 0; u < NT / 2; u++) {
            mma16816(acc[2 * u],          aH0, wf[u]); mma16816(acc[2 * u + 1],      aH0, wf[u] + 2);
            mma16816(acc[NT + 2 * u],     aH1, wf[u]); mma16816(acc[NT + 2 * u + 1], aH1, wf[u] + 2);
        }
    }
}

__device__ __forceinline__ void st_pair(uint32_t hB, uint32_t lB, int p, int o,
                                        float v0, float v1) {
    uint32_t h, l;
    asm("cvt.rn.bf16x2.f32 %0, %1, %2;" : "=r"(h) : "f"(v1), "f"(v0));
    float h0 = __uint_as_float(h << 16);
    float h1 = __uint_as_float(h & 0xffff0000u);
    asm("cvt.rn.bf16x2.f32 %0, %1, %2;" : "=r"(l) : "f"(v1 - h1), "f"(v0 - h0));
    uint32_t off = swz((uint32_t)(p * 128 + 2 * o));
    asm volatile("st.shared.b32 [%0], %1;" :: "r"(hB + off), "r"(h) : "memory");
    asm volatile("st.shared.b32 [%0], %1;" :: "r"(lB + off), "r"(l) : "memory");
}

__device__ __forceinline__ void pack_store8(uint32_t addrH, uint32_t addrL, const float* v) {
    uint32_t h[4], l[4];
    #pragma unroll
    for (int q = 0; q < 4; q++) {
        float a = v[2 * q], b = v[2 * q + 1];
        asm("cvt.rn.bf16x2.f32 %0, %1, %2;" : "=r"(h[q]) : "f"(b), "f"(a));
        float ha = __uint_as_float(h[q] << 16);
        float hb = __uint_as_float(h[q] & 0xffff0000u);
        asm("cvt.rn.bf16x2.f32 %0, %1, %2;" : "=r"(l[q]) : "f"(b - hb), "f"(a - ha));
    }
    asm volatile("st.shared.v4.b32 [%0], {%1, %2, %3, %4};"
                 :: "r"(addrH), "r"(h[0]), "r"(h[1]), "r"(h[2]), "r"(h[3]) : "memory");
    asm volatile("st.shared.v4.b32 [%0], {%1, %2, %3, %4};"
                 :: "r"(addrL), "r"(l[0]), "r"(l[1]), "r"(l[2]), "r"(l[3]) : "memory");
}

// ---------------- K0 ----------------
__global__ void k_init() {
    int i = blockIdx.x * 256 + threadIdx.x;
    if (i < Bv * 2 * Mv) d_csum[i] = 0.f;
    if (i < Bv * Mv)     d_ccnt[i] = 0.f;
    if (i < 130 * P2)    d_g[i]    = 0.f;
}

// zero gp accumulators (graph-replay safe)
__global__ void k_zero() {
    int i = blockIdx.x * 256 + threadIdx.x;        // 512*P2 threads
    if (i < 256 * P2) { d_A[i] = 0.f; d_B2[i] = 0.f; }
    d_C2[i] = 0.f;
    d_D2[i] = 0.f;
}

// ---------------- K1: top-3 + cluster accumulation ----------
__global__ void k_topk(const float* __restrict__ x, const float* __restrict__ node) {
    int idx = blockIdx.x * 256 + threadIdx.x;
    if (idx >= Bv * Nv) return;
    int b = idx >> 12, n = idx & (Nv - 1);
    float x0 = x[b * 2 * Nv + n];
    float x1 = x[b * 2 * Nv + Nv + n];
    float d0 = 3.4e38f, d1 = 3.4e38f, d2 = 3.4e38f;
    int   i0 = 0, i1 = 0, i2 = 0;
    #pragma unroll
    for (int m = 0; m < Mv; m++) {
        float dx = x0 - __ldg(&node[b * 2 * Mv + m]);
        float dy = x1 - __ldg(&node[b * 2 * Mv + Mv + m]);
        float d = dx * dx + dy * dy;
        if (d < d0)      { d2 = d1; i2 = i1; d1 = d0; i1 = i0; d0 = d; i0 = m; }
        else if (d < d1) { d2 = d1; i2 = i1; d1 = d;  i1 = m; }
        else if (d < d2) { d2 = d;  i2 = m; }
    }
    int o = idx * 3;
    d_topk[o] = i0; d_topk[o + 1] = i1; d_topk[o + 2] = i2;
    atomicAdd(&d_csum[b * 2 * Mv + i0],      x0);
    atomicAdd(&d_csum[b * 2 * Mv + Mv + i0], x1);
    atomicAdd(&d_ccnt[b * Mv + i0], 1.f);
    atomicAdd(&d_csum[b * 2 * Mv + i1],      x0);
    atomicAdd(&d_csum[b * 2 * Mv + Mv + i1], x1);
    atomicAdd(&d_ccnt[b * Mv + i1], 1.f);
    atomicAdd(&d_csum[b * 2 * Mv + i2],      x0);
    atomicAdd(&d_csum[b * 2 * Mv + Mv + i2], x1);
    atomicAdd(&d_ccnt[b * Mv + i2], 1.f);
}

// ---------------- K2 ----------------
__global__ void k_nodes() {
    int idx = threadIdx.x;
    int b = idx >> 6, m = idx & 63;
    float cnt = d_ccnt[b * Mv + m];
    float inv = 1.f / (cnt + 1e-5f);
    float m0 = d_csum[b * 2 * Mv + m]      * inv;
    float m1 = d_csum[b * 2 * Mv + Mv + m] * inv;
    #pragma unroll
    for (int r = 0; r < Rv; r++) {
        float c, s; rot_cs(r, c, s);
        float n0 = c * m0 - s * m1;
        float n1 = s * m0 + c * m1;
        int br = b * Rv + r;
        d_nrot[(br * 2 + 0) * Mv + m] = n0;
        d_nrot[(br * 2 + 1) * Mv + m] = n1;
        d_g[0 * P2 + br * Mv + m] = n0;
        d_g[1 * P2 + br * Mv + m] = n1;
    }
}

// ---------------- warp-MMA fused fp block (unchanged from R12) -------------
#define OW1H  0
#define OW1L  8192
#define OW2H  16384
#define OW2L  32768
#define OW3AH 49152
#define OW3AL 65536
#define OW3BH 81920
#define OW3BL 98304
#define OGRP  114688
#define OW0F  212992
#define OW3X  213504
#define OB0   214528
#define OB1   214784
#define OB2   215040
#define OB3   215552
#define OXS   216064
#define OMS   217088
#define SMEM_TC 217600

__global__ void __launch_bounds__(512, 1) k_fp_mma(
    const float* __restrict__ x,
    const float* __restrict__ W0, const float* __restrict__ b0,
    const float* __restrict__ W1, const float* __restrict__ b1,
    const float* __restrict__ W2, const float* __restrict__ b2,
    const float* __restrict__ W3, const float* __restrict__ b3)
{
    extern __shared__ __align__(1024) char smc[];
    float* smf = (float*)smc;
    const int tid  = threadIdx.x;
    const int wid  = tid >> 5;
    const int lane = tid & 31;
    const uint32_t sb = smem_u32(smc);

    for (int i = tid; i < 4096; i += 512) {
        int o = i >> 6, k = i & 63;
        float w = W1[o * 64 + k];
        __nv_bfloat16 h = __float2bfloat16(w);
        __nv_bfloat16 l = __float2bfloat16(w - __bfloat162float(h));
        uint32_t off = swz(o * 128 + 2 * k);
        *(__nv_bfloat16*)(smc + OW1H + off) = h;
        *(__nv_bfloat16*)(smc + OW1L + off) = l;
    }
    for (int i = tid; i < 8192; i += 512) {
        int o = i >> 6, k = i & 63;
        float w = W2[o * 64 + k];
        __nv_bfloat16 h = __float2bfloat16(w);
        __nv_bfloat16 l = __float2bfloat16(w - __bfloat162float(h));
        uint32_t off = swz(o * 128 + 2 * k);
        *(__nv_bfloat16*)(smc + OW2H + off) = h;
        *(__nv_bfloat16*)(smc + OW2L + off) = l;
    }
    for (int i = tid; i < 8192; i += 512) {
        int o = i >> 6, k = i & 63;
        float w = W3[o * 130 + 2 + k];
        __nv_bfloat16 h = __float2bfloat16(w);
        __nv_bfloat16 l = __float2bfloat16(w - __bfloat162float(h));
        uint32_t off = swz(o * 128 + 2 * k);
        *(__nv_bfloat16*)(smc + OW3AH + off) = h;
        *(__nv_bfloat16*)(smc + OW3AL + off) = l;
    }
    for (int i = tid; i < 8192; i += 512) {
        int o = i >> 6, k = i & 63;
        float w = W3[o * 130 + 66 + k];
        __nv_bfloat16 h = __float2bfloat16(w);
        __nv_bfloat16 l = __float2bfloat16(w - __bfloat162float(h));
        uint32_t off = swz(o * 128 + 2 * k);
        *(__nv_bfloat16*)(smc + OW3BH + off) = h;
        *(__nv_bfloat16*)(smc + OW3BL + off) = l;
    }
    if (tid < 128) {
        smf[OW0F / 4 + tid] = W0[tid];
        smf[OW3X / 4 + tid]       = W3[tid * 130];
        smf[OW3X / 4 + 128 + tid] = W3[tid * 130 + 1];
        if (tid < 64) { smf[OB0 / 4 + tid] = b0[tid]; smf[OB1 / 4 + tid] = b1[tid]; }
        smf[OB2 / 4 + tid] = b2[tid];
        smf[OB3 / 4 + tid] = b3[tid];
    }
    __syncthreads();

    const int grp  = wid >> 3;
    const int tidg = tid & 255;
    const int wg   = wid & 7;
    const int mp   = wg >> 2;
    const int nq   = wg & 3;
    const int mt0  = 2 * mp;
    const int gq   = lane >> 2;
    const int tq   = lane & 3;

    const uint32_t gb  = sb + OGRP + grp * 49152;
    const uint32_t bAH = gb,          bAL = gb + 8192;
    const uint32_t bRH = gb + 16384,  bRL = gb + 24576;
    const uint32_t bCH = gb + 32768,  bCL = gb + 40960;
    float* xsf = smf + (OXS + grp * 512) / 4;
    int*   ms  = (int*)(smc + OMS + grp * 256);
    const int barid = grp + 1;

    #define GBAR() asm volatile("bar.sync %0, 256;" :: "r"(barid) : "memory")

    for (int t = blockIdx.x * 2 + grp; t < TILES64; t += 296) {
        int br = t / TPB64; int tloc = t - br * TPB64; int kn0 = tloc * 64;
        int b = br >> 2, r = br & 3;

        if (tidg < 64) {
            int kn = kn0 + tidg; int k = kn >> 12; int n = kn & (Nv - 1);
            float x0 = x[b * 2 * Nv + n], x1 = x[b * 2 * Nv + Nv + n];
            float cc, ss; rot_cs(r, cc, ss);
            float xr0 = cc * x0 - ss * x1;
            float xr1 = ss * x0 + cc * x1;
            int m = d_topk[(b * Nv + n) * 3 + k];
            xsf[tidg]      = xr0 - d_nrot[(br * 2 + 0) * Mv + m];
            xsf[64 + tidg] = xr1 - d_nrot[(br * 2 + 1) * Mv + m];
            ms[tidg] = m;
        }
        GBAR();

        {
            int pp = tidg & 63, q = tidg >> 6;
            float x0 = xsf[pp], x1 = xsf[64 + pp];
            float v[16];
            #pragma unroll
            for (int j = 0; j < 16; j++) {
                int o = 16 * q + j;
                v[j] = fmaxf(fmaf(smf[OW0F / 4 + 2 * o], x0,
                             fmaf(smf[OW0F / 4 + 2 * o + 1], x1, smf[OB0 / 4 + o])), 0.f);
            }
            uint32_t ro = pp * 128 + 32 * q;
            pack_store8(bAH + swz(ro),      bAL + swz(ro),      v);
            pack_store8(bAH + swz(ro + 16), bAL + swz(ro + 16), v + 8);
        }
        GBAR();

        {
            float acc[4][4];
            #pragma unroll
            for (int i = 0; i < 4; i++)
                #pragma unroll
                for (int j = 0; j < 4; j++) acc[i][j] = 0.f;
            int n0 = nq * 16;
            mma3p<2>(acc, bAH, bAL, sb + OW1H, sb + OW1L, mt0, n0, lane);
            #pragma unroll
            for (int mt = 0; mt < 2; mt++) {
                int rp = 16 * (mt0 + mt) + gq;
                #pragma unroll
                for (int nt = 0; nt < 2; nt++) {
                    int o = n0 + 8 * nt + 2 * tq;
                    float bv0 = smf[OB1 / 4 + o], bv1 = smf[OB1 / 4 + o + 1];
                    float* a = acc[mt * 2 + nt];
                    st_pair(bRH, bRL, rp, o,
                            fmaxf(a[0] + bv0, 0.f), fmaxf(a[1] + bv1, 0.f));
                    st_pair(bRH, bRL, rp + 8, o,
                            fmaxf(a[2] + bv0, 0.f), fmaxf(a[3] + bv1, 0.f));
                }
            }
        }
        GBAR();

        {
            float acc[8][4];
            #pragma unroll
            for (int i = 0; i < 8; i++)
                #pragma unroll
                for (int j = 0; j < 4; j++) acc[i][j] = 0.f;
            int n0 = nq * 32;
            mma3p<4>(acc, bRH, bRL, sb + OW2H, sb + OW2L, mt0, n0, lane);
            uint32_t hB = (nq < 2) ? bAH : bCH;
            uint32_t lB = (nq < 2) ? bAL : bCL;
            #pragma unroll
            for (int mt = 0; mt < 2; mt++) {
                int rp = 16 * (mt0 + mt) + gq;
                #pragma unroll
                for (int nt = 0; nt < 4; nt++) {
                    int o = n0 + 8 * nt + 2 * tq;
                    float bv0 = smf[OB2 / 4 + o], bv1 = smf[OB2 / 4 + o + 1];
                    int oc = o & 63;
                    float* a = acc[mt * 4 + nt];
                    st_pair(hB, lB, rp, oc,
                            fmaxf(a[0] + bv0, 0.f), fmaxf(a[1] + bv1, 0.f));
                    st_pair(hB, lB, rp + 8, oc,
                            fmaxf(a[2] + bv0, 0.f), fmaxf(a[3] + bv1, 0.f));
                }
            }
        }
        GBAR();

        {
            float acc[8][4];
            #pragma unroll
            for (int i = 0; i < 8; i++)
                #pragma unroll
                for (int j = 0; j < 4; j++) acc[i][j] = 0.f;
            int n0 = nq * 32;
            mma3p<4>(acc, bAH, bAL, sb + OW3AH, sb + OW3AL, mt0, n0, lane);
            mma3p<4>(acc, bCH, bCL, sb + OW3BH, sb + OW3BL, mt0, n0, lane);

            #pragma unroll
            for (int mt = 0; mt < 2; mt++) {
                int rp = 16 * (mt0 + mt) + gq;
                float x0a = xsf[rp],     x1a = xsf[64 + rp];
                float x0b = xsf[rp + 8], x1b = xsf[64 + rp + 8];
                int ma = ms[rp], mb = ms[rp + 8];
                unsigned* gpa = (unsigned*)&d_g[2 * P2 + br * Mv + ma];
                unsigned* gpb = (unsigned*)&d_g[2 * P2 + br * Mv + mb];
                bool put0 = (tloc == 0 && rp == 0);
                #pragma unroll
                for (int nt = 0; nt < 4; nt++) {
                    int o = n0 + 8 * nt + 2 * tq;
                    float w00 = smf[OW3X / 4 + o],     w10 = smf[OW3X / 4 + 128 + o];
                    float w01 = smf[OW3X / 4 + o + 1], w11 = smf[OW3X / 4 + 128 + o + 1];
                    float bv0 = smf[OB3 / 4 + o],      bv1 = smf[OB3 / 4 + o + 1];
                    float* a = acc[mt * 4 + nt];
                    float v0 = fmaxf(a[0] + bv0 + w00 * x0a + w10 * x1a, 0.f);
                    float v1 = fmaxf(a[1] + bv1 + w01 * x0a + w11 * x1a, 0.f);
                    float v2 = fmaxf(a[2] + bv0 + w00 * x0b + w10 * x1b, 0.f);
                    float v3 = fmaxf(a[3] + bv1 + w01 * x0b + w11 * x1b, 0.f);
                    atomicMax(gpa + o * P2,       __float_as_uint(v0));
                    atomicMax(gpa + (o + 1) * P2, __float_as_uint(v1));
                    atomicMax(gpb + o * P2,       __float_as_uint(v2));
                    atomicMax(gpb + (o + 1) * P2, __float_as_uint(v3));
                    if (put0) { d_fcol0[br * 128 + o] = v0; d_fcol0[br * 128 + o + 1] = v1; }
                }
            }
        }
        GBAR();
    }
    #undef GBAR
}

// ---------------- K5: empty-cluster fallback ----------------
__global__ void k_fix() {
    int idx = blockIdx.x * 256 + threadIdx.x;
    int m = idx & 63; int c = (idx >> 6) & 127; int br = idx >> 13;
    int b = br >> 2;
    if (d_ccnt[b * Mv + m] == 0.f)
        d_g[(2 + c) * P2 + br * Mv + m] = d_fcol0[br * 128 + c];
}

// ---------------- gp partial GEMM: 64 outs x 64 cols x K-chunk -> atomicAdd
__global__ void __launch_bounds__(256) k_gemm_part(
    const float* __restrict__ W,
    const float* __restrict__ in1, int C1,
    const float* __restrict__ in2, int C2,
    float* __restrict__ out, int KCH)
{
    __shared__ __align__(16) float Wsh[16][68];
    __shared__ __align__(16) float Ish[16][68];
    const int C = C1 + C2;
    const int col0 = blockIdx.x * 64, ob0 = blockIdx.y * 64;
    const int kbase = blockIdx.z * KCH;
    const int kend = (kbase + KCH < C) ? (kbase + KCH) : C;
    const int tid = threadIdx.x;
    const int og = tid >> 5;            // 0..7 (uniform per warp)
    const int cg = tid & 31;
    const int o0 = og * 8, p0 = cg * 2;
    unsigned long long acc[8];
    #pragma unroll
    for (int i = 0; i < 8; i++) acc[i] = 0ull;

    for (int k0 = kbase; k0 < kend; k0 += 16) {
        #pragma unroll
        for (int q = 0; q < 4; q++) {
            int l = tid * 4 + q; int oo = l >> 4, kk = l & 15;
            int c = k0 + kk;
            Wsh[kk][oo] = (c < kend) ? W[(ob0 + oo) * C + c] : 0.f;
        }
        #pragma unroll
        for (int q = 0; q < 4; q++) {
            int l = tid * 4 + q; int kk = l >> 6, cc = l & 63;
            int c = k0 + kk;
            float v = 0.f;
            if (c < kend) {
                if (c < C1)      v = in1[c * P2 + col0 + cc];
                else             v = in2[(c - C1) * P2 + col0 + cc];
            }
            Ish[kk][cc] = v;
        }
        __syncthreads();
        #pragma unroll
        for (int kk = 0; kk < 16; kk++) {
            float4 wA = *(const float4*)&Wsh[kk][o0];
            float4 wB = *(const float4*)&Wsh[kk][o0 + 4];
            unsigned long long a = *(const unsigned long long*)&Ish[kk][p0];
            acc[0] = ffma2(pack2(wA.x, wA.x), a, acc[0]);
            acc[1] = ffma2(pack2(wA.y, wA.y), a, acc[1]);
            acc[2] = ffma2(pack2(wA.z, wA.z), a, acc[2]);
            acc[3] = ffma2(pack2(wA.w, wA.w), a, acc[3]);
            acc[4] = ffma2(pack2(wB.x, wB.x), a, acc[4]);
            acc[5] = ffma2(pack2(wB.y, wB.y), a, acc[5]);
            acc[6] = ffma2(pack2(wB.z, wB.z), a, acc[6]);
            acc[7] = ffma2(pack2(wB.w, wB.w), a, acc[7]);
        }
        __syncthreads();
    }
    #pragma unroll
    for (int i = 0; i < 8; i++) {
        int o = ob0 + o0 + i;
        atomicAdd(&out[o * P2 + col0 + p0],     lo2(acc[i]));
        atomicAdd(&out[o * P2 + col0 + p0 + 1], hi2(acc[i]));
    }
}

// ---------------- gp epilogue: in-place bias + relu ----------------
__global__ void k_epi(float* __restrict__ buf, const float* __restrict__ bias) {
    int i = blockIdx.x * 256 + threadIdx.x;
    int o = i >> 10;
    buf[i] = fmaxf(buf[i] + bias[o], 0.f);
}

// ---------------- K6: final max over (r, m) ----------------
__global__ void k_reduce(float* __restrict__ out) {
    int idx = blockIdx.x * 256 + threadIdx.x;
    int b = idx >> 9, f = idx & 511;
    const float* src = &d_D2[f * P2 + b * 256];
    float v = 0.f;
    #pragma unroll 8
    for (int j = 0; j < 256; j++) v = fmaxf(v, src[j]);
    out[b * Fv + f] = v;
}

// ---------------- host launcher ----------------
extern "C" void kernel_launch(void* const* d_in, const int* in_sizes, int n_in,
                              void* d_out, int out_size) {
    const float* x    = (const float*)d_in[0];
    const float* node = (const float*)d_in[2];
    const float* fpW0 = (const float*)d_in[4];  const float* fpb0 = (const float*)d_in[5];
    const float* fpW1 = (const float*)d_in[6];  const float* fpb1 = (const float*)d_in[7];
    const float* fpW2 = (const float*)d_in[8];  const float* fpb2 = (const float*)d_in[9];
    const float* fpW3 = (const float*)d_in[10]; const float* fpb3 = (const float*)d_in[11];
    const float* gpW0 = (const float*)d_in[12]; const float* gpb0 = (const float*)d_in[13];
    const float* gpW1 = (const float*)d_in[14]; const float* gpb1 = (const float*)d_in[15];
    const float* gpW2 = (const float*)d_in[16]; const float* gpb2 = (const float*)d_in[17];
    const float* gpW3 = (const float*)d_in[18]; const float* gpb3 = (const float*)d_in[19];

    float *p_g, *p_A, *p_B2, *p_C2, *p_D2;
    cudaGetSymbolAddress((void**)&p_g,  d_g);
    cudaGetSymbolAddress((void**)&p_A,  d_A);
    cudaGetSymbolAddress((void**)&p_B2, d_B2);
    cudaGetSymbolAddress((void**)&p_C2, d_C2);
    cudaGetSymbolAddress((void**)&p_D2, d_D2);

    cudaFuncSetAttribute(k_fp_mma, cudaFuncAttributeMaxDynamicSharedMemorySize, SMEM_TC);

    k_init<<<(130 * P2 + 255) / 256, 256>>>();
    k_zero<<<(512 * P2) / 256, 256>>>();
    k_topk<<<(Bv * Nv) / 256, 256>>>(x, node);
    k_nodes<<<1, 256>>>();

    k_fp_mma<<<148, 512, SMEM_TC>>>(x, fpW0, fpb0, fpW1, fpb1,
                                    fpW2, fpb2, fpW3, fpb3);
    k_fix<<<(BRv * 128 * Mv) / 256, 256>>>();

    // gp block: k-split partial GEMMs + epilogues
    k_gemm_part<<<dim3(16, 4, 2), 256>>>(gpW0, p_g,  130, nullptr, 0, p_A,  65);
    k_epi<<<(256 * P2) / 256, 256>>>(p_A, gpb0);
    k_gemm_part<<<dim3(16, 4, 2), 256>>>(gpW1, p_A,  256, nullptr, 0, p_B2, 128);
    k_epi<<<(256 * P2) / 256, 256>>>(p_B2, gpb1);
    k_gemm_part<<<dim3(16, 8, 2), 256>>>(gpW2, p_B2, 256, nullptr, 0, p_C2, 128);
    k_epi<<<(512 * P2) / 256, 256>>>(p_C2, gpb2);
    k_gemm_part<<<dim3(16, 8, 5), 256>>>(gpW3, p_g,  130, p_C2,  512, p_D2, 129);
    k_epi<<<(512 * P2) / 256, 256>>>(p_D2, gpb3);

    k_reduce<<<(Bv * Fv) / 256, 256>>>((float*)d_out);
}

// round 14
// speedup vs baseline: 1.4109x; 1.0548x over previous
#include <cuda_runtime.h>
#include <cuda_bf16.h>
#include <math.h>
#include <stdint.h>

// ---------------- problem constants ----------------
#define Bv   4
#define Rv   4
#define Nv   4096
#define Mv   64
#define KNv  12288
#define BRv  16
#define P1   196608
#define P2   1024
#define Fv   512
#define TILES64 3072         // P1 / 64
#define TPB64   192          // KN / 64
#define NGROUPS 296

// ---------------- device scratch ----------------
__device__ int   d_topk[Bv * Nv * 3];
__device__ float d_csum[Bv * 2 * Mv];
__device__ float d_ccnt[Bv * Mv];
__device__ float d_g[130 * P2];
__device__ float d_fcol0[BRv * 128];
__device__ float d_A[256 * P2];
__device__ float d_B2[256 * P2];
__device__ float d_C2[512 * P2];
__device__ float d_D2[512 * P2];
__device__ int   d_ctr;

// ---------------- scalar helpers ----------------
__device__ __forceinline__ unsigned long long ffma2(unsigned long long a,
                                                    unsigned long long b,
                                                    unsigned long long c) {
    unsigned long long d;
    asm("fma.rn.f32x2 %0, %1, %2, %3;" : "=l"(d) : "l"(a), "l"(b), "l"(c));
    return d;
}
__device__ __forceinline__ unsigned long long pack2(float lo, float hi) {
    unsigned long long r;
    asm("mov.b64 %0, {%1, %2};" : "=l"(r) : "f"(lo), "f"(hi));
    return r;
}
__device__ __forceinline__ float lo2(unsigned long long a) { return __uint_as_float((unsigned)a); }
__device__ __forceinline__ float hi2(unsigned long long a) { return __uint_as_float((unsigned)(a >> 32)); }

__device__ __forceinline__ void rot_cs(int r, float& c, float& s) {
    float th = 6.2831855f * (float)r * 0.25f;
    c = cosf(th);
    s = sinf(th);
}
__device__ __forceinline__ uint32_t smem_u32(const void* p) {
    uint32_t a;
    asm("{ .reg .u64 t; cvta.to.shared.u64 t, %1; cvt.u32.u64 %0, t; }" : "=r"(a) : "l"(p));
    return a;
}
__device__ __forceinline__ uint32_t swz(uint32_t b) { return b ^ ((b >> 3) & 0x70); }

// ---------------- warp MMA helpers ----------------
__device__ __forceinline__ void ldsm4(uint32_t* r, uint32_t addr) {
    asm volatile("ldmatrix.sync.aligned.m8n8.x4.shared.b16 {%0,%1,%2,%3}, [%4];"
                 : "=r"(r[0]), "=r"(r[1]), "=r"(r[2]), "=r"(r[3]) : "r"(addr));
}
__device__ __forceinline__ void mma16816(float* d, const uint32_t* a, const uint32_t* b) {
    asm volatile("mma.sync.aligned.m16n8k16.row.col.f32.bf16.bf16.f32 "
                 "{%0,%1,%2,%3}, {%4,%5,%6,%7}, {%8,%9}, {%0,%1,%2,%3};"
                 : "+f"(d[0]), "+f"(d[1]), "+f"(d[2]), "+f"(d[3])
                 : "r"(a[0]), "r"(a[1]), "r"(a[2]), "r"(a[3]), "r"(b[0]), "r"(b[1]));
}

// m-paired hi/lo 3-combo pass (as R12)
template<int NT>
__device__ __forceinline__ void mma3p(float acc[][4], uint32_t aHb, uint32_t aLb,
                                      uint32_t wHb, uint32_t wLb, int mt0, int n0, int lane) {
    const int abase = (lane & 7) + ((lane >> 3) & 1) * 8;
    const int aoff = ((lane >> 4) & 1) * 16;
    const int arow0 = 16 * mt0 + abase;
    const int arow1 = arow0 + 16;
    const int brow = (lane & 7) + (lane >> 4) * 8;
    const int boff = ((lane >> 3) & 1) * 16;
    #pragma unroll
    for (int ks = 0; ks < 4; ks++) {
        uint32_t aH0[4], aL0[4], aH1[4], aL1[4];
        uint32_t a0s = swz((uint32_t)(arow0 * 128 + 32 * ks + aoff));
        uint32_t a1s = swz((uint32_t)(arow1 * 128 + 32 * ks + aoff));
        ldsm4(aH0, aHb + a0s);
        ldsm4(aH1, aHb + a1s);
        ldsm4(aL0, aLb + a0s);
        ldsm4(aL1, aLb + a1s);
        uint32_t roffs[NT / 2];
        uint32_t wf[NT / 2][4];
        #pragma unroll
        for (int u = 0; u < NT / 2; u++) {
            roffs[u] = swz((uint32_t)((n0 + 16 * u + brow) * 128 + 32 * ks + boff));
            ldsm4(wf[u], wHb + roffs[u]);
        }
        #pragma unroll
        for (int u = 0; u < NT / 2; u++) {
            mma16816(acc[2 * u],          aH0, wf[u]); mma16816(acc[2 * u + 1],      aH0, wf[u] + 2);
            mma16816(acc[NT + 2 * u],     aH1, wf[u]); mma16816(acc[NT + 2 * u + 1], aH1, wf[u] + 2);
        }
        #pragma unroll
        for (int u = 0; u < NT / 2; u++) {
            mma16816(acc[2 * u],          aL0, wf[u]); mma16816(acc[2 * u + 1],      aL0, wf[u] + 2);
            mma16816(acc[NT + 2 * u],     aL1, wf[u]); mma16816(acc[NT + 2 * u + 1], aL1, wf[u] + 2);
        }
        #pragma unroll
        for (int u = 0; u < NT / 2; u++)
            ldsm4(wf[u], wLb + roffs[u]);
        #pragma unroll
        for (int u = 0; u < NT / 2; u++) {
            mma16816(acc[2 * u],          aH0, wf[u]); mma16816(acc[2 * u + 1],      aH0, wf[u] + 2);
            mma16816(acc[NT + 2 * u],     aH1, wf[u]); mma16816(acc[NT + 2 * u + 1], aH1, wf[u] + 2);
        }
    }
}

__device__ __forceinline__ void st_pair(uint32_t hB, uint32_t lB, int p, int o,
                                        float v0, float v1) {
    uint32_t h, l;
    asm("cvt.rn.bf16x2.f32 %0, %1, %2;" : "=r"(h) : "f"(v1), "f"(v0));
    float h0 = __uint_as_float(h << 16);
    float h1 = __uint_as_float(h & 0xffff0000u);
    asm("cvt.rn.bf16x2.f32 %0, %1, %2;" : "=r"(l) : "f"(v1 - h1), "f"(v0 - h0));
    uint32_t off = swz((uint32_t)(p * 128 + 2 * o));
    asm volatile("st.shared.b32 [%0], %1;" :: "r"(hB + off), "r"(h) : "memory");
    asm volatile("st.shared.b32 [%0], %1;" :: "r"(lB + off), "r"(l) : "memory");
}

__device__ __forceinline__ void pack_store8(uint32_t addrH, uint32_t addrL, const float* v) {
    uint32_t h[4], l[4];
    #pragma unroll
    for (int q = 0; q < 4; q++) {
        float a = v[2 * q], b = v[2 * q + 1];
        asm("cvt.rn.bf16x2.f32 %0, %1, %2;" : "=r"(h[q]) : "f"(b), "f"(a));
        float ha = __uint_as_float(h[q] << 16);
        float hb = __uint_as_float(h[q] & 0xffff0000u);
        asm("cvt.rn.bf16x2.f32 %0, %1, %2;" : "=r"(l[q]) : "f"(b - hb), "f"(a - ha));
    }
    asm volatile("st.shared.v4.b32 [%0], {%1, %2, %3, %4};"
                 :: "r"(addrH), "r"(h[0]), "r"(h[1]), "r"(h[2]), "r"(h[3]) : "memory");
    asm volatile("st.shared.v4.b32 [%0], {%1, %2, %3, %4};"
                 :: "r"(addrL), "r"(l[0]), "r"(l[1]), "r"(l[2]), "r"(l[3]) : "memory");
}

// ---------------- K0: combined init ----------------
__global__ void k_initz() {
    int i = blockIdx.x * 256 + threadIdx.x;        // 512*P2 grid
    if (i == 0) d_ctr = NGROUPS;
    if (i < Bv * 2 * Mv) d_csum[i] = 0.f;
    if (i < Bv * Mv)     d_ccnt[i] = 0.f;
    if (i < 130 * P2)    d_g[i]    = 0.f;
    if (i < 256 * P2) { d_A[i] = 0.f; d_B2[i] = 0.f; }
    d_C2[i] = 0.f;
    d_D2[i] = 0.f;
}

// ---------------- K1: top-3 + cluster accumulation ----------
__global__ void k_topk(const float* __restrict__ x, const float* __restrict__ node) {
    int idx = blockIdx.x * 256 + threadIdx.x;
    if (idx >= Bv * Nv) return;
    int b = idx >> 12, n = idx & (Nv - 1);
    float x0 = x[b * 2 * Nv + n];
    float x1 = x[b * 2 * Nv + Nv + n];
    float d0 = 3.4e38f, d1 = 3.4e38f, d2 = 3.4e38f;
    int   i0 = 0, i1 = 0, i2 = 0;
    #pragma unroll
    for (int m = 0; m < Mv; m++) {
        float dx = x0 - __ldg(&node[b * 2 * Mv + m]);
        float dy = x1 - __ldg(&node[b * 2 * Mv + Mv + m]);
        float d = dx * dx + dy * dy;
        if (d < d0)      { d2 = d1; i2 = i1; d1 = d0; i1 = i0; d0 = d; i0 = m; }
        else if (d < d1) { d2 = d1; i2 = i1; d1 = d;  i1 = m; }
        else if (d < d2) { d2 = d;  i2 = m; }
    }
    int o = idx * 3;
    d_topk[o] = i0; d_topk[o + 1] = i1; d_topk[o + 2] = i2;
    atomicAdd(&d_csum[b * 2 * Mv + i0],      x0);
    atomicAdd(&d_csum[b * 2 * Mv + Mv + i0], x1);
    atomicAdd(&d_ccnt[b * Mv + i0], 1.f);
    atomicAdd(&d_csum[b * 2 * Mv + i1],      x0);
    atomicAdd(&d_csum[b * 2 * Mv + Mv + i1], x1);
    atomicAdd(&d_ccnt[b * Mv + i1], 1.f);
    atomicAdd(&d_csum[b * 2 * Mv + i2],      x0);
    atomicAdd(&d_csum[b * 2 * Mv + Mv + i2], x1);
    atomicAdd(&d_ccnt[b * Mv + i2], 1.f);
}

// ---------------- warp-MMA fused fp block -----------------------------------
#define OW1H  0
#define OW1L  8192
#define OW2H  16384
#define OW2L  32768
#define OW3AH 49152
#define OW3AL 65536
#define OW3BH 81920
#define OW3BL 98304
#define OGRP  114688
#define OW0F  212992
#define OW3X  213504
#define OB0   214528
#define OB1   214784
#define OB2   215040
#define OB3   215552
#define OXS   216064
#define OMS   217088
#define ONRT  217600    // nrot table [BRv][2][Mv] = 8KB
#define OTS   225792    // per-group next-tile int x2
#define SMEM_TC 225824

__global__ void __launch_bounds__(512, 1) k_fp_mma(
    const float* __restrict__ x,
    const float* __restrict__ W0, const float* __restrict__ b0,
    const float* __restrict__ W1, const float* __restrict__ b1,
    const float* __restrict__ W2, const float* __restrict__ b2,
    const float* __restrict__ W3, const float* __restrict__ b3)
{
    extern __shared__ __align__(1024) char smc[];
    float* smf = (float*)smc;
    const int tid  = threadIdx.x;
    const int wid  = tid >> 5;
    const int lane = tid & 31;
    const uint32_t sb = smem_u32(smc);

    for (int i = tid; i < 4096; i += 512) {
        int o = i >> 6, k = i & 63;
        float w = W1[o * 64 + k];
        __nv_bfloat16 h = __float2bfloat16(w);
        __nv_bfloat16 l = __float2bfloat16(w - __bfloat162float(h));
        uint32_t off = swz(o * 128 + 2 * k);
        *(__nv_bfloat16*)(smc + OW1H + off) = h;
        *(__nv_bfloat16*)(smc + OW1L + off) = l;
    }
    for (int i = tid; i < 8192; i += 512) {
        int o = i >> 6, k = i & 63;
        float w = W2[o * 64 + k];
        __nv_bfloat16 h = __float2bfloat16(w);
        __nv_bfloat16 l = __float2bfloat16(w - __bfloat162float(h));
        uint32_t off = swz(o * 128 + 2 * k);
        *(__nv_bfloat16*)(smc + OW2H + off) = h;
        *(__nv_bfloat16*)(smc + OW2L + off) = l;
    }
    for (int i = tid; i < 8192; i += 512) {
        int o = i >> 6, k = i & 63;
        float w = W3[o * 130 + 2 + k];
        __nv_bfloat16 h = __float2bfloat16(w);
        __nv_bfloat16 l = __float2bfloat16(w - __bfloat162float(h));
        uint32_t off = swz(o * 128 + 2 * k);
        *(__nv_bfloat16*)(smc + OW3AH + off) = h;
        *(__nv_bfloat16*)(smc + OW3AL + off) = l;
    }
    for (int i = tid; i < 8192; i += 512) {
        int o = i >> 6, k = i & 63;
        float w = W3[o * 130 + 66 + k];
        __nv_bfloat16 h = __float2bfloat16(w);
        __nv_bfloat16 l = __float2bfloat16(w - __bfloat162float(h));
        uint32_t off = swz(o * 128 + 2 * k);
        *(__nv_bfloat16*)(smc + OW3BH + off) = h;
        *(__nv_bfloat16*)(smc + OW3BL + off) = l;
    }
    if (tid < 128) {
        smf[OW0F / 4 + tid] = W0[tid];
        smf[OW3X / 4 + tid]       = W3[tid * 130];
        smf[OW3X / 4 + 128 + tid] = W3[tid * 130 + 1];
        if (tid < 64) { smf[OB0 / 4 + tid] = b0[tid]; smf[OB1 / 4 + tid] = b1[tid]; }
        smf[OB2 / 4 + tid] = b2[tid];
        smf[OB3 / 4 + tid] = b3[tid];
    }
    // nrot table: [br][2][64]
    if (tid < 256) {
        int b = tid >> 6, m = tid & 63;
        float cnt = d_ccnt[b * Mv + m];
        float inv = 1.f / (cnt + 1e-5f);
        float m0 = d_csum[b * 2 * Mv + m]      * inv;
        float m1 = d_csum[b * 2 * Mv + Mv + m] * inv;
        #pragma unroll
        for (int r = 0; r < Rv; r++) {
            float cc, ss; rot_cs(r, cc, ss);
            int br = b * Rv + r;
            smf[ONRT / 4 + br * 128 + m]      = cc * m0 - ss * m1;
            smf[ONRT / 4 + br * 128 + 64 + m] = ss * m0 + cc * m1;
        }
    }
    __syncthreads();

    const int grp  = wid >> 3;
    const int tidg = tid & 255;
    const int wg   = wid & 7;
    const int mp   = wg >> 2;
    const int nq   = wg & 3;
    const int mt0  = 2 * mp;
    const int gq   = lane >> 2;
    const int tq   = lane & 3;

    const uint32_t gb  = sb + OGRP + grp * 49152;
    const uint32_t bAH = gb,          bAL = gb + 8192;
    const uint32_t bRH = gb + 16384,  bRL = gb + 24576;
    const uint32_t bCH = gb + 32768,  bCL = gb + 40960;
    float* xsf = smf + (OXS + grp * 512) / 4;
    int*   ms  = (int*)(smc + OMS + grp * 256);
    int*   tsh = (int*)(smc + OTS + grp * 4);
    const float* nrt = smf + ONRT / 4;
    const int barid = grp + 1;

    #define GBAR() asm volatile("bar.sync %0, 256;" :: "r"(barid) : "memory")

    int t = blockIdx.x * 2 + grp;
    while (t < TILES64) {
        int br = t / TPB64; int tloc = t - br * TPB64; int kn0 = tloc * 64;
        int b = br >> 2, r = br & 3;

        // ---- P0+L0 merged: each thread recomputes its own xdec ----
        {
            int pp = tidg & 63, q = tidg >> 6;
            int kn = kn0 + pp; int k = kn >> 12; int n = kn & (Nv - 1);
            float x0r = x[b * 2 * Nv + n], x1r = x[b * 2 * Nv + Nv + n];
            float cc, ss; rot_cs(r, cc, ss);
            float xr0 = cc * x0r - ss * x1r;
            float xr1 = ss * x0r + cc * x1r;
            int m = d_topk[(b * Nv + n) * 3 + k];
            float xd0 = xr0 - nrt[br * 128 + m];
            float xd1 = xr1 - nrt[br * 128 + 64 + m];
            if (q == 0) { xsf[pp] = xd0; xsf[64 + pp] = xd1; ms[pp] = m; }
            float v[16];
            #pragma unroll
            for (int j = 0; j < 16; j++) {
                int o = 16 * q + j;
                v[j] = fmaxf(fmaf(smf[OW0F / 4 + 2 * o], xd0,
                             fmaf(smf[OW0F / 4 + 2 * o + 1], xd1, smf[OB0 / 4 + o])), 0.f);
            }
            uint32_t ro = pp * 128 + 32 * q;
            pack_store8(bAH + swz(ro),      bAL + swz(ro),      v);
            pack_store8(bAH + swz(ro + 16), bAL + swz(ro + 16), v + 8);
        }
        GBAR();

        // ---- L1 ----
        {
            float acc[4][4];
            #pragma unroll
            for (int i = 0; i < 4; i++)
                #pragma unroll
                for (int j = 0; j < 4; j++) acc[i][j] = 0.f;
            int n0 = nq * 16;
            mma3p<2>(acc, bAH, bAL, sb + OW1H, sb + OW1L, mt0, n0, lane);
            #pragma unroll
            for (int mt = 0; mt < 2; mt++) {
                int rp = 16 * (mt0 + mt) + gq;
                #pragma unroll
                for (int nt = 0; nt < 2; nt++) {
                    int o = n0 + 8 * nt + 2 * tq;
                    float bv0 = smf[OB1 / 4 + o], bv1 = smf[OB1 / 4 + o + 1];
                    float* a = acc[mt * 2 + nt];
                    st_pair(bRH, bRL, rp, o,
                            fmaxf(a[0] + bv0, 0.f), fmaxf(a[1] + bv1, 0.f));
                    st_pair(bRH, bRL, rp + 8, o,
                            fmaxf(a[2] + bv0, 0.f), fmaxf(a[3] + bv1, 0.f));
                }
            }
        }
        GBAR();

        // ---- L2 ----
        {
            float acc[8][4];
            #pragma unroll
            for (int i = 0; i < 8; i++)
                #pragma unroll
                for (int j = 0; j < 4; j++) acc[i][j] = 0.f;
            int n0 = nq * 32;
            mma3p<4>(acc, bRH, bRL, sb + OW2H, sb + OW2L, mt0, n0, lane);
            uint32_t hB = (nq < 2) ? bAH : bCH;
            uint32_t lB = (nq < 2) ? bAL : bCL;
            #pragma unroll
            for (int mt = 0; mt < 2; mt++) {
                int rp = 16 * (mt0 + mt) + gq;
                #pragma unroll
                for (int nt = 0; nt < 4; nt++) {
                    int o = n0 + 8 * nt + 2 * tq;
                    float bv0 = smf[OB2 / 4 + o], bv1 = smf[OB2 / 4 + o + 1];
                    int oc = o & 63;
                    float* a = acc[mt * 4 + nt];
                    st_pair(hB, lB, rp, oc,
                            fmaxf(a[0] + bv0, 0.f), fmaxf(a[1] + bv1, 0.f));
                    st_pair(hB, lB, rp + 8, oc,
                            fmaxf(a[2] + bv0, 0.f), fmaxf(a[3] + bv1, 0.f));
                }
            }
        }
        GBAR();

        // ---- L3 + scatter-max ----
        {
            float acc[8][4];
            #pragma unroll
            for (int i = 0; i < 8; i++)
                #pragma unroll
                for (int j = 0; j < 4; j++) acc[i][j] = 0.f;
            int n0 = nq * 32;
            mma3p<4>(acc, bAH, bAL, sb + OW3AH, sb + OW3AL, mt0, n0, lane);
            mma3p<4>(acc, bCH, bCL, sb + OW3BH, sb + OW3BL, mt0, n0, lane);

            #pragma unroll
            for (int mt = 0; mt < 2; mt++) {
                int rp = 16 * (mt0 + mt) + gq;
                float x0a = xsf[rp],     x1a = xsf[64 + rp];
                float x0b = xsf[rp + 8], x1b = xsf[64 + rp + 8];
                int ma = ms[rp], mb = ms[rp + 8];
                unsigned* gpa = (unsigned*)&d_g[2 * P2 + br * Mv + ma];
                unsigned* gpb = (unsigned*)&d_g[2 * P2 + br * Mv + mb];
                bool put0 = (tloc == 0 && rp == 0);
                #pragma unroll
                for (int nt = 0; nt < 4; nt++) {
                    int o = n0 + 8 * nt + 2 * tq;
                    float w00 = smf[OW3X / 4 + o],     w10 = smf[OW3X / 4 + 128 + o];
                    float w01 = smf[OW3X / 4 + o + 1], w11 = smf[OW3X / 4 + 128 + o + 1];
                    float bv0 = smf[OB3 / 4 + o],      bv1 = smf[OB3 / 4 + o + 1];
                    float* a = acc[mt * 4 + nt];
                    float v0 = fmaxf(a[0] + bv0 + w00 * x0a + w10 * x1a, 0.f);
                    float v1 = fmaxf(a[1] + bv1 + w01 * x0a + w11 * x1a, 0.f);
                    float v2 = fmaxf(a[2] + bv0 + w00 * x0b + w10 * x1b, 0.f);
                    float v3 = fmaxf(a[3] + bv1 + w01 * x0b + w11 * x1b, 0.f);
                    atomicMax(gpa + o * P2,       __float_as_uint(v0));
                    atomicMax(gpa + (o + 1) * P2, __float_as_uint(v1));
                    atomicMax(gpb + o * P2,       __float_as_uint(v2));
                    atomicMax(gpb + (o + 1) * P2, __float_as_uint(v3));
                    if (put0) { d_fcol0[br * 128 + o] = v0; d_fcol0[br * 128 + o + 1] = v1; }
                }
            }
        }
        if (tidg == 0) *tsh = atomicAdd(&d_ctr, 1);
        GBAR();
        t = *tsh;
    }
    #undef GBAR
}

// ---------------- K5: empty-cluster fallback + d_g rows 0/1 ----------------
__global__ void k_fix() {
    int idx = blockIdx.x * 256 + threadIdx.x;   // 131072 threads
    if (idx < 2048) {                           // rows 0-1 = node_rot
        int m = idx & 63, br = (idx >> 6) & 15, ch = idx >> 10;
        int b = br >> 2, r = br & 3;
        float cnt = d_ccnt[b * Mv + m];
        float inv = 1.f / (cnt + 1e-5f);
        float m0 = d_csum[b * 2 * Mv + m]      * inv;
        float m1 = d_csum[b * 2 * Mv + Mv + m] * inv;
        float cc, ss; rot_cs(r, cc, ss);
        d_g[ch * P2 + br * Mv + m] = ch ? (ss * m0 + cc * m1) : (cc * m0 - ss * m1);
    }
    int m = idx & 63; int c = (idx >> 6) & 127; int br = idx >> 13;
    int b = br >> 2;
    if (d_ccnt[b * Mv + m] == 0.f)
        d_g[(2 + c) * P2 + br * Mv + m] = d_fcol0[br * 128 + c];
}

// ---------------- gp partial GEMM with fused input activation --------------
// in(c) value: raw in1/in2; if biasX != null apply relu(v + biasX[row]).
__global__ void __launch_bounds__(256) k_gemm_part(
    const float* __restrict__ W,
    const float* __restrict__ in1, int C1, const float* __restrict__ bias1,
    const float* __restrict__ in2, int C2, const float* __restrict__ bias2,
    float* __restrict__ out, int KCH)
{
    __shared__ __align__(16) float Wsh[16][68];
    __shared__ __align__(16) float Ish[16][68];
    const int C = C1 + C2;
    const int col0 = blockIdx.x * 64, ob0 = blockIdx.y * 64;
    const int kbase = blockIdx.z * KCH;
    const int kend = (kbase + KCH < C) ? (kbase + KCH) : C;
    const int tid = threadIdx.x;
    const int og = tid >> 5;
    const int cg = tid & 31;
    const int o0 = og * 8, p0 = cg * 2;
    unsigned long long acc[8];
    #pragma unroll
    for (int i = 0; i < 8; i++) acc[i] = 0ull;

    for (int k0 = kbase; k0 < kend; k0 += 16) {
        #pragma unroll
        for (int q = 0; q < 4; q++) {
            int l = tid * 4 + q; int oo = l >> 4, kk = l & 15;
            int c = k0 + kk;
            Wsh[kk][oo] = (c < kend) ? W[(ob0 + oo) * C + c] : 0.f;
        }
        #pragma unroll
        for (int q = 0; q < 4; q++) {
            int l = tid * 4 + q; int kk = l >> 6, cc = l & 63;
            int c = k0 + kk;
            float v = 0.f;
            if (c < kend) {
                if (c < C1) {
                    v = in1[c * P2 + col0 + cc];
                    if (bias1) v = fmaxf(v + bias1[c], 0.f);
                } else {
                    v = in2[(c - C1) * P2 + col0 + cc];
                    if (bias2) v = fmaxf(v + bias2[c - C1], 0.f);
                }
            }
            Ish[kk][cc] = v;
        }
        __syncthreads();
        #pragma unroll
        for (int kk = 0; kk < 16; kk++) {
            float4 wA = *(const float4*)&Wsh[kk][o0];
            float4 wB = *(const float4*)&Wsh[kk][o0 + 4];
            unsigned long long a = *(const unsigned long long*)&Ish[kk][p0];
            acc[0] = ffma2(pack2(wA.x, wA.x), a, acc[0]);
            acc[1] = ffma2(pack2(wA.y, wA.y), a, acc[1]);
            acc[2] = ffma2(pack2(wA.z, wA.z), a, acc[2]);
            acc[3] = ffma2(pack2(wA.w, wA.w), a, acc[3]);
            acc[4] = ffma2(pack2(wB.x, wB.x), a, acc[4]);
            acc[5] = ffma2(pack2(wB.y, wB.y), a, acc[5]);
            acc[6] = ffma2(pack2(wB.z, wB.z), a, acc[6]);
            acc[7] = ffma2(pack2(wB.w, wB.w), a, acc[7]);
        }
        __syncthreads();
    }
    #pragma unroll
    for (int i = 0; i < 8; i++) {
        int o = ob0 + o0 + i;
        atomicAdd(&out[o * P2 + col0 + p0],     lo2(acc[i]));
        atomicAdd(&out[o * P2 + col0 + p0 + 1], hi2(acc[i]));
    }
}

// ---------------- K6: final max over (r, m) with fused bias+relu -----------
__global__ void k_reduce(const float* __restrict__ b3, float* __restrict__ out) {
    int idx = blockIdx.x * 256 + threadIdx.x;
    int b = idx >> 9, f = idx & 511;
    const float* src = &d_D2[f * P2 + b * 256];
    float v = -3.4e38f;
    #pragma unroll 8
    for (int j = 0; j < 256; j++) v = fmaxf(v, src[j]);
    out[b * Fv + f] = fmaxf(v + b3[f], 0.f);
}

// ---------------- host launcher ----------------
extern "C" void kernel_launch(void* const* d_in, const int* in_sizes, int n_in,
                              void* d_out, int out_size) {
    const float* x    = (const float*)d_in[0];
    const float* node = (const float*)d_in[2];
    const float* fpW0 = (const float*)d_in[4];  const float* fpb0 = (const float*)d_in[5];
    const float* fpW1 = (const float*)d_in[6];  const float* fpb1 = (const float*)d_in[7];
    const float* fpW2 = (const float*)d_in[8];  const float* fpb2 = (const float*)d_in[9];
    const float* fpW3 = (const float*)d_in[10]; const float* fpb3 = (const float*)d_in[11];
    const float* gpW0 = (const float*)d_in[12]; const float* gpb0 = (const float*)d_in[13];
    const float* gpW1 = (const float*)d_in[14]; const float* gpb1 = (const float*)d_in[15];
    const float* gpW2 = (const float*)d_in[16]; const float* gpb2 = (const float*)d_in[17];
    const float* gpW3 = (const float*)d_in[18]; const float* gpb3 = (const float*)d_in[19];

    float *p_g, *p_A, *p_B2, *p_C2, *p_D2;
    cudaGetSymbolAddress((void**)&p_g,  d_g);
    cudaGetSymbolAddress((void**)&p_A,  d_A);
    cudaGetSymbolAddress((void**)&p_B2, d_B2);
    cudaGetSymbolAddress((void**)&p_C2, d_C2);
    cudaGetSymbolAddress((void**)&p_D2, d_D2);

    cudaFuncSetAttribute(k_fp_mma, cudaFuncAttributeMaxDynamicSharedMemorySize, SMEM_TC);

    k_initz<<<(512 * P2) / 256, 256>>>();
    k_topk<<<(Bv * Nv) / 256, 256>>>(x, node);

    k_fp_mma<<<148, 512, SMEM_TC>>>(x, fpW0, fpb0, fpW1, fpb1,
                                    fpW2, fpb2, fpW3, fpb3);
    k_fix<<<(BRv * 128 * Mv) / 256, 256>>>();

    // gp block: k-split partial GEMMs, activations fused at load
    k_gemm_part<<<dim3(16, 4, 2), 256>>>(gpW0, p_g,  130, nullptr,
                                         nullptr, 0, nullptr, p_A,  65);
    k_gemm_part<<<dim3(16, 4, 2), 256>>>(gpW1, p_A,  256, gpb0,
                                         nullptr, 0, nullptr, p_B2, 128);
    k_gemm_part<<<dim3(16, 8, 2), 256>>>(gpW2, p_B2, 256, gpb1,
                                         nullptr, 0, nullptr, p_C2, 128);
    k_gemm_part<<<dim3(16, 8, 5), 256>>>(gpW3, p_g,  130, nullptr,
                                         p_C2, 512, gpb2, p_D2, 129);

    k_reduce<<<(Bv * Fv) / 256, 256>>>(gpb3, (float*)d_out);
}